// round 4
// baseline (speedup 1.0000x reference)
#include <cuda_runtime.h>
#include <cuda_bf16.h>
#include <cstdint>

#define NFC   64
#define HWS   64
#define PSZ   8
#define NB    4
#define NT    16
#define NIMG  64      // NB*NT
#define TOK   1024    // NT * 64 patches
#define DIMD  4096    // NFC * PSZ * PSZ

// ---------------- scratch (static device globals; no allocation) -------------
__device__ __align__(128) __nv_bfloat16 g_Qh[NB][TOK][DIMD];
__device__ __align__(128) __nv_bfloat16 g_Ql[NB][TOK][DIMD];
__device__ __align__(128) __nv_bfloat16 g_Kh[NB][TOK][DIMD];
__device__ __align__(128) __nv_bfloat16 g_Kl[NB][TOK][DIMD];
__device__ __align__(128) float         g_V [NB][TOK][DIMD];
__device__ __align__(128) __nv_bfloat16 g_Vth[NB][DIMD][TOK];
__device__ __align__(128) __nv_bfloat16 g_Vtl[NB][DIMD][TOK];
__device__ __align__(128) float         g_S [NB][TOK][TOK];
__device__ __align__(128) __nv_bfloat16 g_Ph[NB][TOK][TOK];
__device__ __align__(128) __nv_bfloat16 g_Pl[NB][TOK][TOK];
__device__ __align__(128) float g_feat[NIMG][NFC][HWS][HWS];
__device__ __align__(128) float g_vwT[576][NFC];   // [(ic*3+ky)*3+kx][oc]
__device__ __align__(128) float g_cwT[576][NFC];

// ======================= helpers ==============================================
__device__ __forceinline__ uint32_t smem_u32(const void* p) {
    uint32_t a;
    asm("{ .reg .u64 t; cvta.to.shared.u64 t, %1; cvt.u32.u64 %0, t; }"
        : "=r"(a) : "l"(p));
    return a;
}
__device__ __forceinline__ void cpa16(uint32_t dst, const void* src) {
    asm volatile("cp.async.cg.shared.global [%0], [%1], 16;"
                 :: "r"(dst), "l"(__cvta_generic_to_global(src)));
}
__device__ __forceinline__ void cpa_commit() { asm volatile("cp.async.commit_group;" ::: "memory"); }
__device__ __forceinline__ void cpa_wait1()  { asm volatile("cp.async.wait_group 1;" ::: "memory"); }
__device__ __forceinline__ void cpa_wait0()  { asm volatile("cp.async.wait_group 0;" ::: "memory"); }

__device__ __forceinline__ void mma16816(float* c, const uint32_t* a, const uint32_t* b) {
    asm volatile(
        "mma.sync.aligned.m16n8k16.row.col.f32.bf16.bf16.f32 "
        "{%0,%1,%2,%3}, {%4,%5,%6,%7}, {%8,%9}, {%0,%1,%2,%3};"
        : "+f"(c[0]), "+f"(c[1]), "+f"(c[2]), "+f"(c[3])
        : "r"(a[0]), "r"(a[1]), "r"(a[2]), "r"(a[3]), "r"(b[0]), "r"(b[1]));
}

// ---------------- kernel 0: transpose conv weights ----------------------------
__global__ void transpose_w_kernel(const float* __restrict__ vw,
                                   const float* __restrict__ cw) {
    int idx = blockIdx.x * blockDim.x + threadIdx.x;
    if (idx < 64 * 576) {
        int oc = idx / 576;
        int r  = idx - oc * 576;
        g_vwT[r][oc] = vw[oc * 576 + r];
        g_cwT[r][oc] = cw[oc * 576 + r];
    }
}

// ---------------- kernel 1: q,k depthwise + v full conv ------------------------
__global__ __launch_bounds__(512) void qkv_kernel(
    const float* __restrict__ x,
    const float* __restrict__ qw, const float* __restrict__ qb,
    const float* __restrict__ kw, const float* __restrict__ kb,
    const float* __restrict__ vb)
{
    extern __shared__ float s[];          // [64][10][66]
    const int img   = blockIdx.x;
    const int ytile = blockIdx.y;
    const int y0    = ytile * 8;
    const int bb    = img >> 4;
    const int tt    = img & 15;
    const int tid   = threadIdx.x;
    const float* xim = x + (size_t)img * NFC * HWS * HWS;

    for (int idx = tid; idx < 64 * 10 * 66; idx += 512) {
        int c  = idx / 660;
        int rr = idx - c * 660;
        int yy = rr / 66;
        int xx = rr - yy * 66;
        int gy = y0 - 1 + yy;
        int gx = xx - 1;
        float v = 0.f;
        if (gy >= 0 && gy < 64 && gx >= 0 && gx < 64)
            v = xim[c * 4096 + gy * 64 + gx];
        s[idx] = v;
    }
    __syncthreads();

    // depthwise q,k (writes bf16 hi/lo split)
    for (int it = 0; it < 64; it++) {
        int c  = it;
        int yy = tid >> 6;
        int xx = tid & 63;
        const float* sp = s + c * 660 + yy * 66 + xx;
        float aq = 0.f, ak = 0.f;
        #pragma unroll
        for (int ky = 0; ky < 3; ky++)
            #pragma unroll
            for (int kx = 0; kx < 3; kx++) {
                float xv = sp[ky * 66 + kx];
                aq = fmaf(xv, qw[c * 9 + ky * 3 + kx], aq);
                ak = fmaf(xv, kw[c * 9 + ky * 3 + kx], ak);
            }
        aq += qb[c];
        ak += kb[c];
        int tok = tt * 64 + ytile * 8 + (xx >> 3);
        int d   = c * 64 + yy * 8 + (xx & 7);
        __nv_bfloat16 qh = __float2bfloat16(aq);
        __nv_bfloat16 kh = __float2bfloat16(ak);
        g_Qh[bb][tok][d] = qh;
        g_Ql[bb][tok][d] = __float2bfloat16(aq - __bfloat162float(qh));
        g_Kh[bb][tok][d] = kh;
        g_Kl[bb][tok][d] = __float2bfloat16(ak - __bfloat162float(kh));
    }

    // v full conv
    const int ocg = tid & 7;
    const int pg  = tid >> 3;
    const int oc0 = ocg << 3;
    const int py  = pg >> 3;
    const int x0  = (pg & 7) << 3;
    float acc[8][8];
    #pragma unroll
    for (int i = 0; i < 8; i++)
        #pragma unroll
        for (int j = 0; j < 8; j++) acc[i][j] = 0.f;

    const float4* wt4 = reinterpret_cast<const float4*>(&g_vwT[0][0]);
    const int wb = oc0 >> 2;
    for (int ic = 0; ic < 64; ic++) {
        const float* sc = s + ic * 660 + py * 66 + x0;
        const float4* wr = wt4 + ic * 144 + wb;
        #pragma unroll
        for (int kk = 0; kk < 9; kk++) {
            const int ky = kk / 3;
            const int kx = kk - ky * 3;
            float4 w0 = wr[kk * 16];
            float4 w1 = wr[kk * 16 + 1];
            float wv[8] = {w0.x, w0.y, w0.z, w0.w, w1.x, w1.y, w1.z, w1.w};
            const float* sp = sc + ky * 66 + kx;
            #pragma unroll
            for (int i = 0; i < 8; i++) {
                float xv = sp[i];
                #pragma unroll
                for (int j = 0; j < 8; j++)
                    acc[i][j] = fmaf(xv, wv[j], acc[i][j]);
            }
        }
    }

    const int tok = tt * 64 + ytile * 8 + (pg & 7);
    float* vrow = &g_V[bb][tok][0];
    #pragma unroll
    for (int j = 0; j < 8; j++) {
        int   oc   = oc0 + j;
        float bias = vb[oc];
        int   d    = oc * 64 + py * 8;
        float4 o0 = make_float4(acc[0][j] + bias, acc[1][j] + bias,
                                acc[2][j] + bias, acc[3][j] + bias);
        float4 o1 = make_float4(acc[4][j] + bias, acc[5][j] + bias,
                                acc[6][j] + bias, acc[7][j] + bias);
        *(float4*)&vrow[d]     = o0;
        *(float4*)&vrow[d + 4] = o1;
    }
}

// ---------------- kernel 1b: transpose+convert V -> Vt hi/lo -------------------
__global__ __launch_bounds__(256) void transposeV_kernel() {
    __shared__ float tile[32][33];
    const int b  = blockIdx.z;
    const int d0 = blockIdx.x * 32;
    const int t0 = blockIdx.y * 32;
    const int tx = threadIdx.x & 31;
    const int ty = threadIdx.x >> 5;
    const float* V = &g_V[b][0][0];
    #pragma unroll
    for (int k = 0; k < 4; k++)
        tile[ty + k * 8][tx] = V[(size_t)(t0 + ty + k * 8) * DIMD + d0 + tx];
    __syncthreads();
    #pragma unroll
    for (int k = 0; k < 4; k++) {
        int d = d0 + ty + k * 8;
        float v = tile[tx][ty + k * 8];
        __nv_bfloat16 h = __float2bfloat16(v);
        g_Vth[b][d][t0 + tx] = h;
        g_Vtl[b][d][t0 + tx] = __float2bfloat16(v - __bfloat162float(h));
    }
}

// ---------------- mma.sync GEMM (both attention GEMMs) -------------------------
// mode 0: S = scale * Q K^T  (M=N=1024, K=4096, NT)
// mode 1: feat = fold(P V)   (M=1024, N=4096, K=1024, B = Vt NT)
// CTA tile 128x128, warp tile 64x32 (2x4 warp grid), K-chunk 32.
// SMEM row stride 40 bf16 (80B) -> conflict-free frag loads + cp.async stores.
#define RS       40                     // row stride (bf16 elems)
#define OFF_AH   0u
#define OFF_AL   10240u                 // 128*80
#define OFF_BH   20480u
#define OFF_BL   30720u
#define STAGE_B  40960u

__device__ __forceinline__ void load_chunk32(
    uint32_t sb, int tid,
    const __nv_bfloat16* Ah, const __nv_bfloat16* Al, int i0,
    const __nv_bfloat16* Bh, const __nv_bfloat16* Bl, int j0,
    int ld, int k0)
{
    #pragma unroll
    for (int u = tid; u < 2048; u += 256) {
        int part = u >> 9;               // 0:Ah 1:Al 2:Bh 3:Bl
        int idx  = u & 511;              // 128 rows * 4 16B-chunks
        int r = idx >> 2, c = idx & 3;
        const __nv_bfloat16* src;
        if      (part == 0) src = Ah + (size_t)(i0 + r) * ld + k0 + c * 8;
        else if (part == 1) src = Al + (size_t)(i0 + r) * ld + k0 + c * 8;
        else if (part == 2) src = Bh + (size_t)(j0 + r) * ld + k0 + c * 8;
        else                src = Bl + (size_t)(j0 + r) * ld + k0 + c * 8;
        cpa16(sb + (uint32_t)part * 10240u + (uint32_t)(r * 80 + c * 16), src);
    }
    cpa_commit();
}

__global__ __launch_bounds__(256, 2) void gemm_mma_kernel(int mode)
{
    extern __shared__ char dsm[];
    const int tid  = threadIdx.x;
    const int wid  = tid >> 5;
    const int lane = tid & 31;
    const int g    = lane >> 2;          // 0..7
    const int t    = lane & 3;           // 0..3
    const int b    = blockIdx.z;
    const int i0   = blockIdx.y * 128;
    const int j0   = blockIdx.x * 128;
    const int wm   = (wid >> 2) * 64;    // warp row base in tile
    const int wn   = (wid & 3) * 32;     // warp col base in tile

    const __nv_bfloat16 *Ah, *Al, *Bh, *Bl;
    int ld, nch;
    if (mode == 0) {
        Ah = &g_Qh[b][0][0]; Al = &g_Ql[b][0][0];
        Bh = &g_Kh[b][0][0]; Bl = &g_Kl[b][0][0];
        ld = DIMD; nch = DIMD / 32;
    } else {
        Ah = &g_Ph[b][0][0]; Al = &g_Pl[b][0][0];
        Bh = &g_Vth[b][0][0]; Bl = &g_Vtl[b][0][0];
        ld = TOK; nch = TOK / 32;
    }

    const uint32_t sbase = smem_u32(dsm);
    float acc[4][4][4];
    #pragma unroll
    for (int mt = 0; mt < 4; mt++)
        #pragma unroll
        for (int nt = 0; nt < 4; nt++)
            #pragma unroll
            for (int q = 0; q < 4; q++) acc[mt][nt][q] = 0.f;

    load_chunk32(sbase,           tid, Ah, Al, i0, Bh, Bl, j0, ld, 0);
    load_chunk32(sbase + STAGE_B, tid, Ah, Al, i0, Bh, Bl, j0, ld, 32);

    for (int it = 0; it < nch; ++it) {
        const int p = it & 1;
        const char* st = dsm + (uint32_t)p * STAGE_B;
        if (it + 1 < nch) cpa_wait1(); else cpa_wait0();
        __syncthreads();

        #pragma unroll
        for (int ks = 0; ks < 32; ks += 16) {
            uint32_t a[4][4], bh[4][2], bl[4][2];
            // A-hi fragments
            #pragma unroll
            for (int mt = 0; mt < 4; mt++) {
                const char* ab = st + OFF_AH + (size_t)(wm + mt * 16 + g) * 80
                               + (size_t)(ks + t * 2) * 2;
                a[mt][0] = *(const uint32_t*)(ab);
                a[mt][1] = *(const uint32_t*)(ab + 8 * 80);
                a[mt][2] = *(const uint32_t*)(ab + 16);
                a[mt][3] = *(const uint32_t*)(ab + 8 * 80 + 16);
            }
            // B-hi fragments
            #pragma unroll
            for (int nt = 0; nt < 4; nt++) {
                const char* bb = st + OFF_BH + (size_t)(wn + nt * 8 + g) * 80
                               + (size_t)(ks + t * 2) * 2;
                bh[nt][0] = *(const uint32_t*)(bb);
                bh[nt][1] = *(const uint32_t*)(bb + 16);
            }
            // hi * hi
            #pragma unroll
            for (int mt = 0; mt < 4; mt++)
                #pragma unroll
                for (int nt = 0; nt < 4; nt++)
                    mma16816(acc[mt][nt], a[mt], bh[nt]);
            // B-lo fragments, hi * lo
            #pragma unroll
            for (int nt = 0; nt < 4; nt++) {
                const char* bb = st + OFF_BL + (size_t)(wn + nt * 8 + g) * 80
                               + (size_t)(ks + t * 2) * 2;
                bl[nt][0] = *(const uint32_t*)(bb);
                bl[nt][1] = *(const uint32_t*)(bb + 16);
            }
            #pragma unroll
            for (int mt = 0; mt < 4; mt++)
                #pragma unroll
                for (int nt = 0; nt < 4; nt++)
                    mma16816(acc[mt][nt], a[mt], bl[nt]);
            // A-lo fragments (reuse a regs), lo * hi
            #pragma unroll
            for (int mt = 0; mt < 4; mt++) {
                const char* ab = st + OFF_AL + (size_t)(wm + mt * 16 + g) * 80
                               + (size_t)(ks + t * 2) * 2;
                a[mt][0] = *(const uint32_t*)(ab);
                a[mt][1] = *(const uint32_t*)(ab + 8 * 80);
                a[mt][2] = *(const uint32_t*)(ab + 16);
                a[mt][3] = *(const uint32_t*)(ab + 8 * 80 + 16);
            }
            #pragma unroll
            for (int mt = 0; mt < 4; mt++)
                #pragma unroll
                for (int nt = 0; nt < 4; nt++)
                    mma16816(acc[mt][nt], a[mt], bh[nt]);
        }
        __syncthreads();
        if (it + 2 < nch)
            load_chunk32(sbase + (uint32_t)p * STAGE_B, tid,
                         Ah, Al, i0, Bh, Bl, j0, ld, (it + 2) * 32);
    }

    // ---------------- epilogue ----------------
    if (mode == 0) {
        float* Sb = &g_S[b][0][0];
        const float scale = 0.015625f;       // 4096^-0.5
        #pragma unroll
        for (int mt = 0; mt < 4; mt++) {
            int r0 = i0 + wm + mt * 16 + g;
            #pragma unroll
            for (int nt = 0; nt < 4; nt++) {
                int col = j0 + wn + nt * 8 + t * 2;
                float2 lo = make_float2(acc[mt][nt][0] * scale, acc[mt][nt][1] * scale);
                float2 hi = make_float2(acc[mt][nt][2] * scale, acc[mt][nt][3] * scale);
                *(float2*)&Sb[(size_t)r0 * TOK + col]       = lo;
                *(float2*)&Sb[(size_t)(r0 + 8) * TOK + col] = hi;
            }
        }
    } else {
        #pragma unroll
        for (int mt = 0; mt < 4; mt++) {
            #pragma unroll
            for (int rr = 0; rr < 2; rr++) {
                int i   = i0 + wm + mt * 16 + g + rr * 8;
                int img = b * 16 + (i >> 6);
                int gh  = (i >> 3) & 7;
                int gw  = i & 7;
                #pragma unroll
                for (int nt = 0; nt < 4; nt++) {
                    int d  = j0 + wn + nt * 8 + t * 2;
                    int oc = d >> 6;
                    int pi = (d >> 3) & 7;
                    int pj = d & 7;
                    float2 o = make_float2(acc[mt][nt][rr * 2], acc[mt][nt][rr * 2 + 1]);
                    *(float2*)&g_feat[img][oc][gh * 8 + pi][gw * 8 + pj] = o;
                }
            }
        }
    }
}

// ---------------- kernel 3: row softmax, writes P hi/lo bf16 -------------------
__global__ __launch_bounds__(128) void softmax_kernel() {
    const int row = blockIdx.x;            // 0..4095
    const float* p = &g_S[0][0][0] + (size_t)row * TOK;
    __nv_bfloat16* ph = &g_Ph[0][0][0] + (size_t)row * TOK;
    __nv_bfloat16* pl = &g_Pl[0][0][0] + (size_t)row * TOK;
    const int tid = threadIdx.x;
    float v[8];
    float m = -1e30f;
    #pragma unroll
    for (int i = 0; i < 8; i++) { v[i] = p[tid + (i << 7)]; m = fmaxf(m, v[i]); }
    #pragma unroll
    for (int o = 16; o > 0; o >>= 1) m = fmaxf(m, __shfl_xor_sync(0xffffffffu, m, o));
    __shared__ float redm[4], reds[4];
    if ((tid & 31) == 0) redm[tid >> 5] = m;
    __syncthreads();
    m = fmaxf(fmaxf(redm[0], redm[1]), fmaxf(redm[2], redm[3]));
    float sum = 0.f;
    #pragma unroll
    for (int i = 0; i < 8; i++) { v[i] = __expf(v[i] - m); sum += v[i]; }
    #pragma unroll
    for (int o = 16; o > 0; o >>= 1) sum += __shfl_xor_sync(0xffffffffu, sum, o);
    if ((tid & 31) == 0) reds[tid >> 5] = sum;
    __syncthreads();
    sum = reds[0] + reds[1] + reds[2] + reds[3];
    float inv = 1.0f / sum;
    #pragma unroll
    for (int i = 0; i < 8; i++) {
        float pv = v[i] * inv;
        __nv_bfloat16 h = __float2bfloat16(pv);
        ph[tid + (i << 7)] = h;
        pl[tid + (i << 7)] = __float2bfloat16(pv - __bfloat162float(h));
    }
}

// ---------------- kernel 5: final conv + residual ------------------------------
__global__ __launch_bounds__(512) void convc_kernel(
    const float* __restrict__ x,
    const float* __restrict__ cb,
    float* __restrict__ out)
{
    extern __shared__ float s[];          // [64][10][66]
    const int img   = blockIdx.x;
    const int ytile = blockIdx.y;
    const int y0    = ytile * 8;
    const int tid   = threadIdx.x;
    const float* fim = &g_feat[img][0][0][0];

    for (int idx = tid; idx < 64 * 10 * 66; idx += 512) {
        int c  = idx / 660;
        int rr = idx - c * 660;
        int yy = rr / 66;
        int xx = rr - yy * 66;
        int gy = y0 - 1 + yy;
        int gx = xx - 1;
        float v = 0.f;
        if (gy >= 0 && gy < 64 && gx >= 0 && gx < 64)
            v = fim[c * 4096 + gy * 64 + gx];
        s[idx] = v;
    }
    __syncthreads();

    const int ocg = tid & 7;
    const int pg  = tid >> 3;
    const int oc0 = ocg << 3;
    const int py  = pg >> 3;
    const int x0  = (pg & 7) << 3;
    float acc[8][8];
    #pragma unroll
    for (int i = 0; i < 8; i++)
        #pragma unroll
        for (int j = 0; j < 8; j++) acc[i][j] = 0.f;

    const float4* wt4 = reinterpret_cast<const float4*>(&g_cwT[0][0]);
    const int wb = oc0 >> 2;
    for (int ic = 0; ic < 64; ic++) {
        const float* sc = s + ic * 660 + py * 66 + x0;
        const float4* wr = wt4 + ic * 144 + wb;
        #pragma unroll
        for (int kk = 0; kk < 9; kk++) {
            const int ky = kk / 3;
            const int kx = kk - ky * 3;
            float4 w0 = wr[kk * 16];
            float4 w1 = wr[kk * 16 + 1];
            float wv[8] = {w0.x, w0.y, w0.z, w0.w, w1.x, w1.y, w1.z, w1.w};
            const float* sp = sc + ky * 66 + kx;
            #pragma unroll
            for (int i = 0; i < 8; i++) {
                float xv = sp[i];
                #pragma unroll
                for (int j = 0; j < 8; j++)
                    acc[i][j] = fmaf(xv, wv[j], acc[i][j]);
            }
        }
    }

    const int yout = y0 + py;
    #pragma unroll
    for (int j = 0; j < 8; j++) {
        int   oc   = oc0 + j;
        float bias = cb[oc];
        int   base = ((img * 64 + oc) * 64 + yout) * 64 + x0;
        float4 xr0 = *(const float4*)&x[base];
        float4 xr1 = *(const float4*)&x[base + 4];
        float4 o0  = make_float4(acc[0][j] + bias + xr0.x, acc[1][j] + bias + xr0.y,
                                 acc[2][j] + bias + xr0.z, acc[3][j] + bias + xr0.w);
        float4 o1  = make_float4(acc[4][j] + bias + xr1.x, acc[5][j] + bias + xr1.y,
                                 acc[6][j] + bias + xr1.z, acc[7][j] + bias + xr1.w);
        *(float4*)&out[base]     = o0;
        *(float4*)&out[base + 4] = o1;
    }
}

// ---------------- launcher ----------------------------------------------------
extern "C" void kernel_launch(void* const* d_in, const int* in_sizes, int n_in,
                              void* d_out, int out_size) {
    (void)in_sizes; (void)n_in; (void)out_size;
    const float* x  = (const float*)d_in[0];
    const float* qw = (const float*)d_in[1];
    const float* qb = (const float*)d_in[2];
    const float* kw = (const float*)d_in[3];
    const float* kb = (const float*)d_in[4];
    const float* vw = (const float*)d_in[5];
    const float* vb = (const float*)d_in[6];
    const float* cw = (const float*)d_in[7];
    const float* cb = (const float*)d_in[8];
    float* out = (float*)d_out;

    const int smem  = 64 * 10 * 66 * sizeof(float);   // 168,960 B
    const int gsmem = 2 * (int)STAGE_B;               // 81,920 B
    cudaFuncSetAttribute(qkv_kernel,      cudaFuncAttributeMaxDynamicSharedMemorySize, smem);
    cudaFuncSetAttribute(convc_kernel,    cudaFuncAttributeMaxDynamicSharedMemorySize, smem);
    cudaFuncSetAttribute(gemm_mma_kernel, cudaFuncAttributeMaxDynamicSharedMemorySize, gsmem);

    transpose_w_kernel<<<(64 * 576 + 255) / 256, 256>>>(vw, cw);
    qkv_kernel<<<dim3(64, 8), 512, smem>>>(x, qw, qb, kw, kb, vb);
    transposeV_kernel<<<dim3(DIMD / 32, TOK / 32, NB), 256>>>();
    gemm_mma_kernel<<<dim3(8, 8, NB), 256, gsmem>>>(0);    // S = QK^T * scale
    softmax_kernel<<<NB * TOK, 128>>>();
    gemm_mma_kernel<<<dim3(32, 8, NB), 256, gsmem>>>(1);   // feat = fold(P V)
    convc_kernel<<<dim3(64, 8), 512, smem>>>(x, cb, out);
}

// round 6
// speedup vs baseline: 1.5143x; 1.5143x over previous
#include <cuda_runtime.h>
#include <cuda_bf16.h>
#include <cstdint>

#define NFC   64
#define HWS   64
#define PSZ   8
#define NB    4
#define NT    16
#define NIMG  64      // NB*NT
#define TOK   1024    // NT * 64 patches
#define DIMD  4096    // NFC * PSZ * PSZ

typedef unsigned long long u64c;

// ---------------- scratch (static device globals; no allocation) -------------
__device__ __align__(128) __nv_bfloat16 g_Qh[NB][TOK][DIMD];
__device__ __align__(128) __nv_bfloat16 g_Ql[NB][TOK][DIMD];
__device__ __align__(128) __nv_bfloat16 g_Kh[NB][TOK][DIMD];
__device__ __align__(128) __nv_bfloat16 g_Kl[NB][TOK][DIMD];
__device__ __align__(128) float         g_V [NB][TOK][DIMD];
__device__ __align__(128) __nv_bfloat16 g_Vth[NB][DIMD][TOK];
__device__ __align__(128) __nv_bfloat16 g_Vtl[NB][DIMD][TOK];
__device__ __align__(128) float         g_S [NB][TOK][TOK];
__device__ __align__(128) __nv_bfloat16 g_Ph[NB][TOK][TOK];
__device__ __align__(128) __nv_bfloat16 g_Pl[NB][TOK][TOK];
__device__ __align__(128) float g_feat[NIMG][NFC][HWS][HWS];
__device__ __align__(128) float g_vwT[576][NFC];   // [(ic*3+ky)*3+kx][oc]
__device__ __align__(128) float g_cwT[576][NFC];

// ======================= helpers ==============================================
__device__ __forceinline__ uint32_t smem_u32(const void* p) {
    uint32_t a;
    asm("{ .reg .u64 t; cvta.to.shared.u64 t, %1; cvt.u32.u64 %0, t; }"
        : "=r"(a) : "l"(p));
    return a;
}
__device__ __forceinline__ void cpa16(uint32_t dst, const void* src) {
    asm volatile("cp.async.cg.shared.global [%0], [%1], 16;"
                 :: "r"(dst), "l"(__cvta_generic_to_global(src)));
}
__device__ __forceinline__ void cpa_commit() { asm volatile("cp.async.commit_group;" ::: "memory"); }
__device__ __forceinline__ void cpa_wait1()  { asm volatile("cp.async.wait_group 1;" ::: "memory"); }
__device__ __forceinline__ void cpa_wait0()  { asm volatile("cp.async.wait_group 0;" ::: "memory"); }

__device__ __forceinline__ void mma16816(float* c, const uint32_t* a, const uint32_t* b) {
    asm volatile(
        "mma.sync.aligned.m16n8k16.row.col.f32.bf16.bf16.f32 "
        "{%0,%1,%2,%3}, {%4,%5,%6,%7}, {%8,%9}, {%0,%1,%2,%3};"
        : "+f"(c[0]), "+f"(c[1]), "+f"(c[2]), "+f"(c[3])
        : "r"(a[0]), "r"(a[1]), "r"(a[2]), "r"(a[3]), "r"(b[0]), "r"(b[1]));
}
__device__ __forceinline__ void ldsm4(uint32_t* r, uint32_t addr) {
    asm volatile("ldmatrix.sync.aligned.m8n8.x4.shared.b16 {%0,%1,%2,%3}, [%4];"
                 : "=r"(r[0]), "=r"(r[1]), "=r"(r[2]), "=r"(r[3]) : "r"(addr));
}

// packed fp32x2 FMA (Blackwell FFMA2 path)
__device__ __forceinline__ u64c fma2(u64c a, u64c b, u64c c) {
    u64c d;
    asm("fma.rn.f32x2 %0, %1, %2, %3;" : "=l"(d) : "l"(a), "l"(b), "l"(c));
    return d;
}
__device__ __forceinline__ u64c bcast2(float x) {
    u64c d;
    asm("mov.b64 %0, {%1, %1};" : "=l"(d) : "r"(__float_as_uint(x)));
    return d;
}
__device__ __forceinline__ void unpack2(u64c v, float& lo, float& hi) {
    uint32_t l, h;
    asm("mov.b64 {%0, %1}, %2;" : "=r"(l), "=r"(h) : "l"(v));
    lo = __uint_as_float(l);
    hi = __uint_as_float(h);
}

// ---------------- kernel 0: transpose conv weights ----------------------------
__global__ void transpose_w_kernel(const float* __restrict__ vw,
                                   const float* __restrict__ cw) {
    int idx = blockIdx.x * blockDim.x + threadIdx.x;
    if (idx < 64 * 576) {
        int oc = idx / 576;
        int r  = idx - oc * 576;
        g_vwT[r][oc] = vw[oc * 576 + r];
        g_cwT[r][oc] = cw[oc * 576 + r];
    }
}

// -------- shared conv inner: 8 px x 8 oc tile via f32x2 (oc-paired) -----------
__device__ __forceinline__ void conv_tile_f32x2(
    const float* s, const float* wT, int oc0, int py, int x0, float accf[8][8])
{
    u64c acc2[8][4];
    #pragma unroll
    for (int i = 0; i < 8; i++)
        #pragma unroll
        for (int j = 0; j < 4; j++) acc2[i][j] = 0ull;

    for (int ic = 0; ic < 64; ic++) {
        const float* sc = s + ic * 660 + py * 66 + x0;
        const float* wbase = wT + (size_t)(ic * 9) * NFC + oc0;
        #pragma unroll
        for (int kk = 0; kk < 9; kk++) {
            const int ky = kk / 3;
            const int kx = kk - ky * 3;
            const ulonglong2* wv = (const ulonglong2*)(wbase + kk * NFC);
            ulonglong2 p0 = wv[0];
            ulonglong2 p1 = wv[1];
            u64c w0 = p0.x, w1 = p0.y, w2 = p1.x, w3 = p1.y;
            const float* sp = sc + ky * 66 + kx;
            #pragma unroll
            for (int i = 0; i < 8; i++) {
                u64c xv = bcast2(sp[i]);
                acc2[i][0] = fma2(xv, w0, acc2[i][0]);
                acc2[i][1] = fma2(xv, w1, acc2[i][1]);
                acc2[i][2] = fma2(xv, w2, acc2[i][2]);
                acc2[i][3] = fma2(xv, w3, acc2[i][3]);
            }
        }
    }
    #pragma unroll
    for (int i = 0; i < 8; i++)
        #pragma unroll
        for (int j = 0; j < 4; j++)
            unpack2(acc2[i][j], accf[i][2 * j], accf[i][2 * j + 1]);
}

// ---------------- kernel 1: q,k depthwise + v full conv ------------------------
__global__ __launch_bounds__(512) void qkv_kernel(
    const float* __restrict__ x,
    const float* __restrict__ qw, const float* __restrict__ qb,
    const float* __restrict__ kw, const float* __restrict__ kb,
    const float* __restrict__ vb)
{
    extern __shared__ float s[];          // [64][10][66]
    const int img   = blockIdx.x;
    const int ytile = blockIdx.y;
    const int y0    = ytile * 8;
    const int bb    = img >> 4;
    const int tt    = img & 15;
    const int tid   = threadIdx.x;
    const float* xim = x + (size_t)img * NFC * HWS * HWS;

    for (int idx = tid; idx < 64 * 10 * 66; idx += 512) {
        int c  = idx / 660;
        int rr = idx - c * 660;
        int yy = rr / 66;
        int xx = rr - yy * 66;
        int gy = y0 - 1 + yy;
        int gx = xx - 1;
        float v = 0.f;
        if (gy >= 0 && gy < 64 && gx >= 0 && gx < 64)
            v = xim[c * 4096 + gy * 64 + gx];
        s[idx] = v;
    }
    __syncthreads();

    // depthwise q,k (writes bf16 hi/lo split)
    for (int it = 0; it < 64; it++) {
        int c  = it;
        int yy = tid >> 6;
        int xx = tid & 63;
        const float* sp = s + c * 660 + yy * 66 + xx;
        float aq = 0.f, ak = 0.f;
        #pragma unroll
        for (int ky = 0; ky < 3; ky++)
            #pragma unroll
            for (int kx = 0; kx < 3; kx++) {
                float xv = sp[ky * 66 + kx];
                aq = fmaf(xv, qw[c * 9 + ky * 3 + kx], aq);
                ak = fmaf(xv, kw[c * 9 + ky * 3 + kx], ak);
            }
        aq += qb[c];
        ak += kb[c];
        int tok = tt * 64 + ytile * 8 + (xx >> 3);
        int d   = c * 64 + yy * 8 + (xx & 7);
        __nv_bfloat16 qh = __float2bfloat16(aq);
        __nv_bfloat16 kh = __float2bfloat16(ak);
        g_Qh[bb][tok][d] = qh;
        g_Ql[bb][tok][d] = __float2bfloat16(aq - __bfloat162float(qh));
        g_Kh[bb][tok][d] = kh;
        g_Kl[bb][tok][d] = __float2bfloat16(ak - __bfloat162float(kh));
    }

    // v full conv (f32x2)
    const int ocg = tid & 7;
    const int pg  = tid >> 3;
    const int oc0 = ocg << 3;
    const int py  = pg >> 3;
    const int x0  = (pg & 7) << 3;
    float acc[8][8];
    conv_tile_f32x2(s, &g_vwT[0][0], oc0, py, x0, acc);

    const int tok = tt * 64 + ytile * 8 + (pg & 7);
    float* vrow = &g_V[bb][tok][0];
    #pragma unroll
    for (int j = 0; j < 8; j++) {
        int   oc   = oc0 + j;
        float bias = vb[oc];
        int   d    = oc * 64 + py * 8;
        float4 o0 = make_float4(acc[0][j] + bias, acc[1][j] + bias,
                                acc[2][j] + bias, acc[3][j] + bias);
        float4 o1 = make_float4(acc[4][j] + bias, acc[5][j] + bias,
                                acc[6][j] + bias, acc[7][j] + bias);
        *(float4*)&vrow[d]     = o0;
        *(float4*)&vrow[d + 4] = o1;
    }
}

// ---------------- kernel 1b: transpose+convert V -> Vt hi/lo -------------------
__global__ __launch_bounds__(256) void transposeV_kernel() {
    __shared__ float tile[32][33];
    const int b  = blockIdx.z;
    const int d0 = blockIdx.x * 32;
    const int t0 = blockIdx.y * 32;
    const int tx = threadIdx.x & 31;
    const int ty = threadIdx.x >> 5;
    const float* V = &g_V[b][0][0];
    #pragma unroll
    for (int k = 0; k < 4; k++)
        tile[ty + k * 8][tx] = V[(size_t)(t0 + ty + k * 8) * DIMD + d0 + tx];
    __syncthreads();
    #pragma unroll
    for (int k = 0; k < 4; k++) {
        int d = d0 + ty + k * 8;
        float v = tile[tx][ty + k * 8];
        __nv_bfloat16 h = __float2bfloat16(v);
        g_Vth[b][d][t0 + tx] = h;
        g_Vtl[b][d][t0 + tx] = __float2bfloat16(v - __bfloat162float(h));
    }
}

// ---------------- mma.sync GEMM (both attention GEMMs) -------------------------
// CTA tile 128x128, warp tile 64x32 (2x4 warp grid), K-chunk 32.
// SMEM row stride 40 bf16 (80B) -> conflict-free ldmatrix + cp.async stores.
#define OFF_AH   0u
#define OFF_AL   10240u                 // 128*80
#define OFF_BH   20480u
#define OFF_BL   30720u
#define STAGE_B  40960u

__device__ __forceinline__ void load_chunk32(
    uint32_t sb, int tid,
    const __nv_bfloat16* Ah, const __nv_bfloat16* Al, int i0,
    const __nv_bfloat16* Bh, const __nv_bfloat16* Bl, int j0,
    int ld, int k0)
{
    #pragma unroll
    for (int u = tid; u < 2048; u += 256) {
        int part = u >> 9;               // 0:Ah 1:Al 2:Bh 3:Bl
        int idx  = u & 511;              // 128 rows * 4 16B-chunks
        int r = idx >> 2, c = idx & 3;
        const __nv_bfloat16* src;
        if      (part == 0) src = Ah + (size_t)(i0 + r) * ld + k0 + c * 8;
        else if (part == 1) src = Al + (size_t)(i0 + r) * ld + k0 + c * 8;
        else if (part == 2) src = Bh + (size_t)(j0 + r) * ld + k0 + c * 8;
        else                src = Bl + (size_t)(j0 + r) * ld + k0 + c * 8;
        cpa16(sb + (uint32_t)part * 10240u + (uint32_t)(r * 80 + c * 16), src);
    }
    cpa_commit();
}

__global__ __launch_bounds__(256, 2) void gemm_mma_kernel(int mode)
{
    extern __shared__ char dsm[];
    const int tid  = threadIdx.x;
    const int wid  = tid >> 5;
    const int lane = tid & 31;
    const int g    = lane >> 2;          // 0..7
    const int t    = lane & 3;           // 0..3
    const int b    = blockIdx.z;
    const int i0   = blockIdx.y * 128;
    const int j0   = blockIdx.x * 128;
    const int wm   = (wid >> 2) * 64;    // warp row base in tile
    const int wn   = (wid & 3) * 32;     // warp col base in tile
    const int lrow = lane & 15;          // ldmatrix row within 16
    const int lk   = (lane >> 4) << 3;   // ldmatrix k-half

    const __nv_bfloat16 *Ah, *Al, *Bh, *Bl;
    int ld, nch;
    if (mode == 0) {
        Ah = &g_Qh[b][0][0]; Al = &g_Ql[b][0][0];
        Bh = &g_Kh[b][0][0]; Bl = &g_Kl[b][0][0];
        ld = DIMD; nch = DIMD / 32;
    } else {
        Ah = &g_Ph[b][0][0]; Al = &g_Pl[b][0][0];
        Bh = &g_Vth[b][0][0]; Bl = &g_Vtl[b][0][0];
        ld = TOK; nch = TOK / 32;
    }

    const uint32_t sbase = smem_u32(dsm);
    float acc[4][4][4];
    #pragma unroll
    for (int mt = 0; mt < 4; mt++)
        #pragma unroll
        for (int nt = 0; nt < 4; nt++)
            #pragma unroll
            for (int q = 0; q < 4; q++) acc[mt][nt][q] = 0.f;

    load_chunk32(sbase,           tid, Ah, Al, i0, Bh, Bl, j0, ld, 0);
    load_chunk32(sbase + STAGE_B, tid, Ah, Al, i0, Bh, Bl, j0, ld, 32);

    for (int it = 0; it < nch; ++it) {
        const int p = it & 1;
        const uint32_t st = sbase + (uint32_t)p * STAGE_B;
        if (it + 1 < nch) cpa_wait1(); else cpa_wait0();
        __syncthreads();

        #pragma unroll
        for (int ks = 0; ks < 32; ks += 16) {
            uint32_t a[4][4], bh2[2][4], bl2[2][4];
            const uint32_t cofs = (uint32_t)((ks + lk) * 2);
            // A-hi fragments via ldmatrix.x4
            #pragma unroll
            for (int mt = 0; mt < 4; mt++)
                ldsm4(a[mt], st + OFF_AH + (uint32_t)((wm + mt * 16 + lrow) * 80) + cofs);
            // B-hi fragments (two n16 groups cover 4 n8 tiles)
            #pragma unroll
            for (int ntp = 0; ntp < 2; ntp++)
                ldsm4(bh2[ntp], st + OFF_BH + (uint32_t)((wn + ntp * 16 + lrow) * 80) + cofs);
            // hi * hi
            #pragma unroll
            for (int mt = 0; mt < 4; mt++)
                #pragma unroll
                for (int nt = 0; nt < 4; nt++) {
                    uint32_t bf[2] = { bh2[nt >> 1][nt & 1], bh2[nt >> 1][(nt & 1) + 2] };
                    mma16816(acc[mt][nt], a[mt], bf);
                }
            // B-lo fragments, hi * lo
            #pragma unroll
            for (int ntp = 0; ntp < 2; ntp++)
                ldsm4(bl2[ntp], st + OFF_BL + (uint32_t)((wn + ntp * 16 + lrow) * 80) + cofs);
            #pragma unroll
            for (int mt = 0; mt < 4; mt++)
                #pragma unroll
                for (int nt = 0; nt < 4; nt++) {
                    uint32_t bf[2] = { bl2[nt >> 1][nt & 1], bl2[nt >> 1][(nt & 1) + 2] };
                    mma16816(acc[mt][nt], a[mt], bf);
                }
            // A-lo fragments (reuse regs), lo * hi
            #pragma unroll
            for (int mt = 0; mt < 4; mt++)
                ldsm4(a[mt], st + OFF_AL + (uint32_t)((wm + mt * 16 + lrow) * 80) + cofs);
            #pragma unroll
            for (int mt = 0; mt < 4; mt++)
                #pragma unroll
                for (int nt = 0; nt < 4; nt++) {
                    uint32_t bf[2] = { bh2[nt >> 1][nt & 1], bh2[nt >> 1][(nt & 1) + 2] };
                    mma16816(acc[mt][nt], a[mt], bf);
                }
        }
        __syncthreads();
        if (it + 2 < nch)
            load_chunk32(sbase + (uint32_t)p * STAGE_B, tid,
                         Ah, Al, i0, Bh, Bl, j0, ld, (it + 2) * 32);
    }

    // ---------------- epilogue ----------------
    if (mode == 0) {
        float* Sb = &g_S[b][0][0];
        const float scale = 0.015625f;       // 4096^-0.5
        #pragma unroll
        for (int mt = 0; mt < 4; mt++) {
            int r0 = i0 + wm + mt * 16 + g;
            #pragma unroll
            for (int nt = 0; nt < 4; nt++) {
                int col = j0 + wn + nt * 8 + t * 2;
                float2 lo = make_float2(acc[mt][nt][0] * scale, acc[mt][nt][1] * scale);
                float2 hi = make_float2(acc[mt][nt][2] * scale, acc[mt][nt][3] * scale);
                *(float2*)&Sb[(size_t)r0 * TOK + col]       = lo;
                *(float2*)&Sb[(size_t)(r0 + 8) * TOK + col] = hi;
            }
        }
    } else {
        #pragma unroll
        for (int mt = 0; mt < 4; mt++) {
            #pragma unroll
            for (int rr = 0; rr < 2; rr++) {
                int i   = i0 + wm + mt * 16 + g + rr * 8;
                int img = b * 16 + (i >> 6);
                int gh  = (i >> 3) & 7;
                int gw  = i & 7;
                #pragma unroll
                for (int nt = 0; nt < 4; nt++) {
                    int d  = j0 + wn + nt * 8 + t * 2;
                    int oc = d >> 6;
                    int pi = (d >> 3) & 7;
                    int pj = d & 7;
                    float2 o = make_float2(acc[mt][nt][rr * 2], acc[mt][nt][rr * 2 + 1]);
                    *(float2*)&g_feat[img][oc][gh * 8 + pi][gw * 8 + pj] = o;
                }
            }
        }
    }
}

// ---------------- kernel 3: row softmax, writes P hi/lo bf16 -------------------
__global__ __launch_bounds__(128) void softmax_kernel() {
    const int row = blockIdx.x;            // 0..4095
    const float* p = &g_S[0][0][0] + (size_t)row * TOK;
    __nv_bfloat16* ph = &g_Ph[0][0][0] + (size_t)row * TOK;
    __nv_bfloat16* pl = &g_Pl[0][0][0] + (size_t)row * TOK;
    const int tid = threadIdx.x;
    float v[8];
    float m = -1e30f;
    #pragma unroll
    for (int i = 0; i < 8; i++) { v[i] = p[tid + (i << 7)]; m = fmaxf(m, v[i]); }
    #pragma unroll
    for (int o = 16; o > 0; o >>= 1) m = fmaxf(m, __shfl_xor_sync(0xffffffffu, m, o));
    __shared__ float redm[4], reds[4];
    if ((tid & 31) == 0) redm[tid >> 5] = m;
    __syncthreads();
    m = fmaxf(fmaxf(redm[0], redm[1]), fmaxf(redm[2], redm[3]));
    float sum = 0.f;
    #pragma unroll
    for (int i = 0; i < 8; i++) { v[i] = __expf(v[i] - m); sum += v[i]; }
    #pragma unroll
    for (int o = 16; o > 0; o >>= 1) sum += __shfl_xor_sync(0xffffffffu, sum, o);
    if ((tid & 31) == 0) reds[tid >> 5] = sum;
    __syncthreads();
    sum = reds[0] + reds[1] + reds[2] + reds[3];
    float inv = 1.0f / sum;
    #pragma unroll
    for (int i = 0; i < 8; i++) {
        float pv = v[i] * inv;
        __nv_bfloat16 h = __float2bfloat16(pv);
        ph[tid + (i << 7)] = h;
        pl[tid + (i << 7)] = __float2bfloat16(pv - __bfloat162float(h));
    }
}

// ---------------- kernel 5: final conv + residual ------------------------------
__global__ __launch_bounds__(512) void convc_kernel(
    const float* __restrict__ x,
    const float* __restrict__ cb,
    float* __restrict__ out)
{
    extern __shared__ float s[];          // [64][10][66]
    const int img   = blockIdx.x;
    const int ytile = blockIdx.y;
    const int y0    = ytile * 8;
    const int tid   = threadIdx.x;
    const float* fim = &g_feat[img][0][0][0];

    for (int idx = tid; idx < 64 * 10 * 66; idx += 512) {
        int c  = idx / 660;
        int rr = idx - c * 660;
        int yy = rr / 66;
        int xx = rr - yy * 66;
        int gy = y0 - 1 + yy;
        int gx = xx - 1;
        float v = 0.f;
        if (gy >= 0 && gy < 64 && gx >= 0 && gx < 64)
            v = fim[c * 4096 + gy * 64 + gx];
        s[idx] = v;
    }
    __syncthreads();

    const int ocg = tid & 7;
    const int pg  = tid >> 3;
    const int oc0 = ocg << 3;
    const int py  = pg >> 3;
    const int x0  = (pg & 7) << 3;
    float acc[8][8];
    conv_tile_f32x2(s, &g_cwT[0][0], oc0, py, x0, acc);

    const int yout = y0 + py;
    #pragma unroll
    for (int j = 0; j < 8; j++) {
        int   oc   = oc0 + j;
        float bias = cb[oc];
        int   base = ((img * 64 + oc) * 64 + yout) * 64 + x0;
        float4 xr0 = *(const float4*)&x[base];
        float4 xr1 = *(const float4*)&x[base + 4];
        float4 o0  = make_float4(acc[0][j] + bias + xr0.x, acc[1][j] + bias + xr0.y,
                                 acc[2][j] + bias + xr0.z, acc[3][j] + bias + xr0.w);
        float4 o1  = make_float4(acc[4][j] + bias + xr1.x, acc[5][j] + bias + xr1.y,
                                 acc[6][j] + bias + xr1.z, acc[7][j] + bias + xr1.w);
        *(float4*)&out[base]     = o0;
        *(float4*)&out[base + 4] = o1;
    }
}

// ---------------- launcher ----------------------------------------------------
extern "C" void kernel_launch(void* const* d_in, const int* in_sizes, int n_in,
                              void* d_out, int out_size) {
    (void)in_sizes; (void)n_in; (void)out_size;
    const float* x  = (const float*)d_in[0];
    const float* qw = (const float*)d_in[1];
    const float* qb = (const float*)d_in[2];
    const float* kw = (const float*)d_in[3];
    const float* kb = (const float*)d_in[4];
    const float* vw = (const float*)d_in[5];
    const float* vb = (const float*)d_in[6];
    const float* cw = (const float*)d_in[7];
    const float* cb = (const float*)d_in[8];
    float* out = (float*)d_out;

    const int smem  = 64 * 10 * 66 * sizeof(float);   // 168,960 B
    const int gsmem = 2 * (int)STAGE_B;               // 81,920 B
    cudaFuncSetAttribute(qkv_kernel,      cudaFuncAttributeMaxDynamicSharedMemorySize, smem);
    cudaFuncSetAttribute(convc_kernel,    cudaFuncAttributeMaxDynamicSharedMemorySize, smem);
    cudaFuncSetAttribute(gemm_mma_kernel, cudaFuncAttributeMaxDynamicSharedMemorySize, gsmem);

    transpose_w_kernel<<<(64 * 576 + 255) / 256, 256>>>(vw, cw);
    qkv_kernel<<<dim3(64, 8), 512, smem>>>(x, qw, qb, kw, kb, vb);
    transposeV_kernel<<<dim3(DIMD / 32, TOK / 32, NB), 256>>>();
    gemm_mma_kernel<<<dim3(8, 8, NB), 256, gsmem>>>(0);    // S = QK^T * scale
    softmax_kernel<<<NB * TOK, 128>>>();
    gemm_mma_kernel<<<dim3(32, 8, NB), 256, gsmem>>>(1);   // feat = fold(P V)
    convc_kernel<<<dim3(64, 8), 512, smem>>>(x, cb, out);
}

// round 7
// speedup vs baseline: 1.6784x; 1.1084x over previous
#include <cuda_runtime.h>
#include <cuda_bf16.h>
#include <cstdint>

#define NFC   64
#define HWS   64
#define PSZ   8
#define NB    4
#define NT    16
#define NIMG  64      // NB*NT
#define TOK   1024    // NT * 64 patches
#define DIMD  4096    // NFC * PSZ * PSZ

// ---------------- scratch (static device globals; no allocation) -------------
__device__ __align__(128) __nv_bfloat16 g_Qh[NB][TOK][DIMD];
__device__ __align__(128) __nv_bfloat16 g_Ql[NB][TOK][DIMD];
__device__ __align__(128) __nv_bfloat16 g_Kh[NB][TOK][DIMD];
__device__ __align__(128) __nv_bfloat16 g_Kl[NB][TOK][DIMD];
__device__ __align__(128) float         g_V [NB][TOK][DIMD];
__device__ __align__(128) __nv_bfloat16 g_Vth[NB][DIMD][TOK];
__device__ __align__(128) __nv_bfloat16 g_Vtl[NB][DIMD][TOK];
__device__ __align__(128) float         g_S [NB][TOK][TOK];
__device__ __align__(128) __nv_bfloat16 g_Ph[NB][TOK][TOK];
__device__ __align__(128) __nv_bfloat16 g_Pl[NB][TOK][TOK];
__device__ __align__(128) float g_feat[NIMG][NFC][HWS][HWS];
// conv weights as [tap][oc][ic] bf16 hi/lo, pre-swizzled for ldmatrix
__device__ __align__(128) __nv_bfloat16 g_Wvh[9 * 4096];
__device__ __align__(128) __nv_bfloat16 g_Wvl[9 * 4096];
__device__ __align__(128) __nv_bfloat16 g_Wch[9 * 4096];
__device__ __align__(128) __nv_bfloat16 g_Wcl[9 * 4096];

// ======================= helpers ==============================================
__device__ __forceinline__ uint32_t smem_u32(const void* p) {
    uint32_t a;
    asm("{ .reg .u64 t; cvta.to.shared.u64 t, %1; cvt.u32.u64 %0, t; }"
        : "=r"(a) : "l"(p));
    return a;
}
__device__ __forceinline__ void cpa16(uint32_t dst, const void* src) {
    asm volatile("cp.async.cg.shared.global [%0], [%1], 16;"
                 :: "r"(dst), "l"(__cvta_generic_to_global(src)));
}
__device__ __forceinline__ void cpa_commit() { asm volatile("cp.async.commit_group;" ::: "memory"); }
__device__ __forceinline__ void cpa_wait1()  { asm volatile("cp.async.wait_group 1;" ::: "memory"); }
__device__ __forceinline__ void cpa_wait0()  { asm volatile("cp.async.wait_group 0;" ::: "memory"); }

__device__ __forceinline__ void mma16816(float* c, const uint32_t* a, const uint32_t* b) {
    asm volatile(
        "mma.sync.aligned.m16n8k16.row.col.f32.bf16.bf16.f32 "
        "{%0,%1,%2,%3}, {%4,%5,%6,%7}, {%8,%9}, {%0,%1,%2,%3};"
        : "+f"(c[0]), "+f"(c[1]), "+f"(c[2]), "+f"(c[3])
        : "r"(a[0]), "r"(a[1]), "r"(a[2]), "r"(a[3]), "r"(b[0]), "r"(b[1]));
}
__device__ __forceinline__ void ldsm4(uint32_t* r, uint32_t addr) {
    asm volatile("ldmatrix.sync.aligned.m8n8.x4.shared.b16 {%0,%1,%2,%3}, [%4];"
                 : "=r"(r[0]), "=r"(r[1]), "=r"(r[2]), "=r"(r[3]) : "r"(addr));
}

// ---------------- kernel 0: prep conv weights (hi/lo, swizzled) ---------------
__global__ void prep_w_kernel(const float* __restrict__ vw,
                              const float* __restrict__ cw) {
    int idx = blockIdx.x * blockDim.x + threadIdx.x;
    if (idx < 9 * 64 * 64) {
        int t   = idx >> 12;
        int rem = idx & 4095;
        int oc  = rem >> 6;
        int ic  = rem & 63;
        int di  = t * 4096 + oc * 64 + (ic ^ ((oc & 7) << 3));
        float v = vw[oc * 576 + ic * 9 + t];
        __nv_bfloat16 h = __float2bfloat16(v);
        g_Wvh[di] = h;
        g_Wvl[di] = __float2bfloat16(v - __bfloat162float(h));
        v = cw[oc * 576 + ic * 9 + t];
        h = __float2bfloat16(v);
        g_Wch[di] = h;
        g_Wcl[di] = __float2bfloat16(v - __bfloat162float(h));
    }
}

// ---------------- implicit-GEMM conv (tensor cores), both convs ---------------
// mode 0 (V): src = x image; also computes depthwise q/k; writes g_V (+vb)
// mode 1 (C): src = g_feat; writes out = conv + cb + residual x
// CTA: one image x one 8-row tile. X tile in smem as [660 px][64 ic] bf16 h/l,
// XOR-swizzled 128B rows. 9 taps, each M=512 N=64 K=64 GEMM, 3 hi/lo terms.
#define CG_XH    0u
#define CG_XL    84480u
#define CG_W     168960u       // + stage*16384 ; hi at +0, lo at +8192
#define CG_SMEM  201728
#define DB_PITCH 520

__global__ __launch_bounds__(512) void conv_gemm_kernel(
    int mode,
    const float* __restrict__ xin,
    const float* __restrict__ qw, const float* __restrict__ qb,
    const float* __restrict__ kw, const float* __restrict__ kb,
    const float* __restrict__ bias,
    float* __restrict__ out)
{
    extern __shared__ char sm[];
    const uint32_t sb = smem_u32(sm);
    const int img   = blockIdx.x;
    const int ytile = blockIdx.y;
    const int y0    = ytile * 8;
    const int tid   = threadIdx.x;
    const int wid   = tid >> 5;
    const int lane  = tid & 31;
    const int lrow  = lane & 15;
    const int lhi   = lane >> 4;
    const int wy    = wid >> 1;          // warp y-row (0..7)
    const int wx0   = (wid & 1) * 32;    // warp x base

    const float* src = (mode == 0) ? (xin + (size_t)img * NFC * HWS * HWS)
                                   : &g_feat[img][0][0][0];
    const __nv_bfloat16* Wh = (mode == 0) ? g_Wvh : g_Wch;
    const __nv_bfloat16* Wl = (mode == 0) ? g_Wvl : g_Wcl;

    // prefetch weight taps 0,1 (cp.async groups)
    #pragma unroll
    for (int s = 0; s < 2; s++) {
        for (int u = tid; u < 1024; u += 512) {
            int term = u >> 9, off = (u & 511) * 16;
            const char* gsrc = (const char*)((term ? Wl : Wh) + s * 4096) + off;
            cpa16(sb + CG_W + (uint32_t)s * 16384u + (uint32_t)(term * 8192 + off), gsrc);
        }
        cpa_commit();
    }

    // load X halo tile -> bf16 hi/lo swizzled [r][c]
    for (int base = 0; base < 42240; base += 512) {
        int idx = base + tid;
        if (idx < 42240) {
            int c  = idx / 660;
            int r  = idx - c * 660;
            int yy = r / 66;
            int xx = r - yy * 66;
            int gy = y0 - 1 + yy, gx = xx - 1;
            float v = 0.f;
            if (gy >= 0 && gy < 64 && gx >= 0 && gx < 64)
                v = src[c * 4096 + gy * 64 + gx];
            __nv_bfloat16 h = __float2bfloat16(v);
            __nv_bfloat16 l = __float2bfloat16(v - __bfloat162float(h));
            uint32_t o = (uint32_t)(r * 128 + 2 * (c ^ ((r & 7) << 3)));
            *(__nv_bfloat16*)(sm + CG_XH + o) = h;
            *(__nv_bfloat16*)(sm + CG_XL + o) = l;
        }
    }
    __syncthreads();

    // depthwise q/k from reconstructed tile (mode 0 only)
    if (mode == 0) {
        const int bb = img >> 4, tt = img & 15;
        const int yy = tid >> 6, xx = tid & 63;
        const int tok = tt * 64 + ytile * 8 + (xx >> 3);
        for (int c = 0; c < 64; c++) {
            float aq = 0.f, ak = 0.f;
            #pragma unroll
            for (int ky = 0; ky < 3; ky++)
                #pragma unroll
                for (int kx = 0; kx < 3; kx++) {
                    int r = (yy + ky) * 66 + xx + kx;
                    uint32_t o = (uint32_t)(r * 128 + 2 * (c ^ ((r & 7) << 3)));
                    float xv = __bfloat162float(*(const __nv_bfloat16*)(sm + CG_XH + o))
                             + __bfloat162float(*(const __nv_bfloat16*)(sm + CG_XL + o));
                    aq = fmaf(xv, qw[c * 9 + ky * 3 + kx], aq);
                    ak = fmaf(xv, kw[c * 9 + ky * 3 + kx], ak);
                }
            aq += qb[c];
            ak += kb[c];
            int d = c * 64 + yy * 8 + (xx & 7);
            __nv_bfloat16 qh = __float2bfloat16(aq);
            __nv_bfloat16 kh = __float2bfloat16(ak);
            g_Qh[bb][tok][d] = qh;
            g_Ql[bb][tok][d] = __float2bfloat16(aq - __bfloat162float(qh));
            g_Kh[bb][tok][d] = kh;
            g_Kl[bb][tok][d] = __float2bfloat16(ak - __bfloat162float(kh));
        }
    }

    // ---- main MMA loop over 9 taps ----
    float acc[2][8][4];
    #pragma unroll
    for (int mt = 0; mt < 2; mt++)
        #pragma unroll
        for (int nt = 0; nt < 8; nt++)
            #pragma unroll
            for (int q = 0; q < 4; q++) acc[mt][nt][q] = 0.f;

    for (int tap = 0; tap < 9; tap++) {
        const int ky = tap / 3;
        const int kx = tap - ky * 3;
        if (tap + 1 < 9) cpa_wait1(); else cpa_wait0();
        __syncthreads();
        const uint32_t wbuf = sb + CG_W + (uint32_t)(tap & 1) * 16384u;
        const int rbase = (wy + ky) * 66 + wx0 + lrow + kx;

        #pragma unroll
        for (int ks = 0; ks < 4; ks++) {
            const uint32_t cofs = (uint32_t)(ks * 32 + lhi * 16);
            uint32_t a[2][4], bh[4][4], bl[4][4];
            #pragma unroll
            for (int mt = 0; mt < 2; mt++) {
                int r = rbase + mt * 16;
                ldsm4(a[mt], sb + CG_XH + (uint32_t)(r * 128)
                             + (cofs ^ ((uint32_t)(r & 7) << 4)));
            }
            #pragma unroll
            for (int np = 0; np < 4; np++) {
                int o = np * 16 + lrow;
                ldsm4(bh[np], wbuf + (uint32_t)(o * 128)
                              + (cofs ^ ((uint32_t)(o & 7) << 4)));
            }
            #pragma unroll
            for (int mt = 0; mt < 2; mt++)
                #pragma unroll
                for (int nt = 0; nt < 8; nt++) {
                    uint32_t bf[2] = { bh[nt >> 1][nt & 1], bh[nt >> 1][(nt & 1) + 2] };
                    mma16816(acc[mt][nt], a[mt], bf);
                }
            #pragma unroll
            for (int np = 0; np < 4; np++) {
                int o = np * 16 + lrow;
                ldsm4(bl[np], wbuf + 8192u + (uint32_t)(o * 128)
                              + (cofs ^ ((uint32_t)(o & 7) << 4)));
            }
            #pragma unroll
            for (int mt = 0; mt < 2; mt++)
                #pragma unroll
                for (int nt = 0; nt < 8; nt++) {
                    uint32_t bf[2] = { bl[nt >> 1][nt & 1], bl[nt >> 1][(nt & 1) + 2] };
                    mma16816(acc[mt][nt], a[mt], bf);
                }
            #pragma unroll
            for (int mt = 0; mt < 2; mt++) {
                int r = rbase + mt * 16;
                ldsm4(a[mt], sb + CG_XL + (uint32_t)(r * 128)
                             + (cofs ^ ((uint32_t)(r & 7) << 4)));
            }
            #pragma unroll
            for (int mt = 0; mt < 2; mt++)
                #pragma unroll
                for (int nt = 0; nt < 8; nt++) {
                    uint32_t bf[2] = { bh[nt >> 1][nt & 1], bh[nt >> 1][(nt & 1) + 2] };
                    mma16816(acc[mt][nt], a[mt], bf);
                }
        }
        __syncthreads();
        if (tap + 2 < 9) {
            const int tp = tap + 2;
            const uint32_t dbuf = sb + CG_W + (uint32_t)(tp & 1) * 16384u;
            for (int u = tid; u < 1024; u += 512) {
                int term = u >> 9, off = (u & 511) * 16;
                const char* gsrc = (const char*)((term ? Wl : Wh) + tp * 4096) + off;
                cpa16(dbuf + (uint32_t)(term * 8192 + off), gsrc);
            }
            cpa_commit();
        }
    }

    // ---- stage D through smem (X area is dead now), then coalesced writeout ---
    float* Dbuf = (float*)sm;
    const int g  = lane >> 2;
    const int tq = lane & 3;
    #pragma unroll
    for (int mt = 0; mt < 2; mt++)
        #pragma unroll
        for (int rr = 0; rr < 2; rr++) {
            int px = wy * 64 + wx0 + mt * 16 + g + rr * 8;
            #pragma unroll
            for (int nt = 0; nt < 8; nt++) {
                int oc = nt * 8 + tq * 2;
                Dbuf[oc * DB_PITCH + px]       = acc[mt][nt][rr * 2];
                Dbuf[(oc + 1) * DB_PITCH + px] = acc[mt][nt][rr * 2 + 1];
            }
        }
    __syncthreads();

    if (mode == 0) {
        const int bb = img >> 4, tt = img & 15;
        const int tokbase = tt * 64 + ytile * 8;
        for (int e = tid; e < 32768; e += 512) {
            int xb = e >> 12, d = e & 4095;
            int oc = d >> 6, y = (d >> 3) & 7, xa = d & 7;
            g_V[bb][tokbase + xb][d] =
                Dbuf[oc * DB_PITCH + y * 64 + xb * 8 + xa] + bias[oc];
        }
    } else {
        for (int e = tid; e < 32768; e += 512) {
            int oc = e >> 9, y = (e >> 6) & 7, xx = e & 63;
            int gb = ((img * 64 + oc) * 64 + y0 + y) * 64 + xx;
            out[gb] = Dbuf[oc * DB_PITCH + y * 64 + xx] + bias[oc] + xin[gb];
        }
    }
}

// ---------------- kernel 1b: transpose+convert V -> Vt hi/lo -------------------
__global__ __launch_bounds__(256) void transposeV_kernel() {
    __shared__ float tile[32][33];
    const int b  = blockIdx.z;
    const int d0 = blockIdx.x * 32;
    const int t0 = blockIdx.y * 32;
    const int tx = threadIdx.x & 31;
    const int ty = threadIdx.x >> 5;
    const float* V = &g_V[b][0][0];
    #pragma unroll
    for (int k = 0; k < 4; k++)
        tile[ty + k * 8][tx] = V[(size_t)(t0 + ty + k * 8) * DIMD + d0 + tx];
    __syncthreads();
    #pragma unroll
    for (int k = 0; k < 4; k++) {
        int d = d0 + ty + k * 8;
        float v = tile[tx][ty + k * 8];
        __nv_bfloat16 h = __float2bfloat16(v);
        g_Vth[b][d][t0 + tx] = h;
        g_Vtl[b][d][t0 + tx] = __float2bfloat16(v - __bfloat162float(h));
    }
}

// ---------------- mma.sync GEMM (both attention GEMMs) -------------------------
#define OFF_AH   0u
#define OFF_AL   10240u                 // 128*80
#define OFF_BH   20480u
#define OFF_BL   30720u
#define STAGE_B  40960u

__device__ __forceinline__ void load_chunk32(
    uint32_t sb, int tid,
    const __nv_bfloat16* Ah, const __nv_bfloat16* Al, int i0,
    const __nv_bfloat16* Bh, const __nv_bfloat16* Bl, int j0,
    int ld, int k0)
{
    #pragma unroll
    for (int u = tid; u < 2048; u += 256) {
        int part = u >> 9;               // 0:Ah 1:Al 2:Bh 3:Bl
        int idx  = u & 511;              // 128 rows * 4 16B-chunks
        int r = idx >> 2, c = idx & 3;
        const __nv_bfloat16* src;
        if      (part == 0) src = Ah + (size_t)(i0 + r) * ld + k0 + c * 8;
        else if (part == 1) src = Al + (size_t)(i0 + r) * ld + k0 + c * 8;
        else if (part == 2) src = Bh + (size_t)(j0 + r) * ld + k0 + c * 8;
        else                src = Bl + (size_t)(j0 + r) * ld + k0 + c * 8;
        cpa16(sb + (uint32_t)part * 10240u + (uint32_t)(r * 80 + c * 16), src);
    }
    cpa_commit();
}

__global__ __launch_bounds__(256, 2) void gemm_mma_kernel(int mode)
{
    extern __shared__ char dsm[];
    const int tid  = threadIdx.x;
    const int wid  = tid >> 5;
    const int lane = tid & 31;
    const int g    = lane >> 2;          // 0..7
    const int t    = lane & 3;           // 0..3
    const int b    = blockIdx.z;
    const int i0   = blockIdx.y * 128;
    const int j0   = blockIdx.x * 128;
    const int wm   = (wid >> 2) * 64;
    const int wn   = (wid & 3) * 32;
    const int lrow = lane & 15;
    const int lk   = (lane >> 4) << 3;

    const __nv_bfloat16 *Ah, *Al, *Bh, *Bl;
    int ld, nch;
    if (mode == 0) {
        Ah = &g_Qh[b][0][0]; Al = &g_Ql[b][0][0];
        Bh = &g_Kh[b][0][0]; Bl = &g_Kl[b][0][0];
        ld = DIMD; nch = DIMD / 32;
    } else {
        Ah = &g_Ph[b][0][0]; Al = &g_Pl[b][0][0];
        Bh = &g_Vth[b][0][0]; Bl = &g_Vtl[b][0][0];
        ld = TOK; nch = TOK / 32;
    }

    const uint32_t sbase = smem_u32(dsm);
    float acc[4][4][4];
    #pragma unroll
    for (int mt = 0; mt < 4; mt++)
        #pragma unroll
        for (int nt = 0; nt < 4; nt++)
            #pragma unroll
            for (int q = 0; q < 4; q++) acc[mt][nt][q] = 0.f;

    load_chunk32(sbase,           tid, Ah, Al, i0, Bh, Bl, j0, ld, 0);
    load_chunk32(sbase + STAGE_B, tid, Ah, Al, i0, Bh, Bl, j0, ld, 32);

    for (int it = 0; it < nch; ++it) {
        const int p = it & 1;
        const uint32_t st = sbase + (uint32_t)p * STAGE_B;
        if (it + 1 < nch) cpa_wait1(); else cpa_wait0();
        __syncthreads();

        #pragma unroll
        for (int ks = 0; ks < 32; ks += 16) {
            uint32_t a[4][4], bh2[2][4], bl2[2][4];
            const uint32_t cofs = (uint32_t)((ks + lk) * 2);
            #pragma unroll
            for (int mt = 0; mt < 4; mt++)
                ldsm4(a[mt], st + OFF_AH + (uint32_t)((wm + mt * 16 + lrow) * 80) + cofs);
            #pragma unroll
            for (int ntp = 0; ntp < 2; ntp++)
                ldsm4(bh2[ntp], st + OFF_BH + (uint32_t)((wn + ntp * 16 + lrow) * 80) + cofs);
            #pragma unroll
            for (int mt = 0; mt < 4; mt++)
                #pragma unroll
                for (int nt = 0; nt < 4; nt++) {
                    uint32_t bf[2] = { bh2[nt >> 1][nt & 1], bh2[nt >> 1][(nt & 1) + 2] };
                    mma16816(acc[mt][nt], a[mt], bf);
                }
            #pragma unroll
            for (int ntp = 0; ntp < 2; ntp++)
                ldsm4(bl2[ntp], st + OFF_BL + (uint32_t)((wn + ntp * 16 + lrow) * 80) + cofs);
            #pragma unroll
            for (int mt = 0; mt < 4; mt++)
                #pragma unroll
                for (int nt = 0; nt < 4; nt++) {
                    uint32_t bf[2] = { bl2[nt >> 1][nt & 1], bl2[nt >> 1][(nt & 1) + 2] };
                    mma16816(acc[mt][nt], a[mt], bf);
                }
            #pragma unroll
            for (int mt = 0; mt < 4; mt++)
                ldsm4(a[mt], st + OFF_AL + (uint32_t)((wm + mt * 16 + lrow) * 80) + cofs);
            #pragma unroll
            for (int mt = 0; mt < 4; mt++)
                #pragma unroll
                for (int nt = 0; nt < 4; nt++) {
                    uint32_t bf[2] = { bh2[nt >> 1][nt & 1], bh2[nt >> 1][(nt & 1) + 2] };
                    mma16816(acc[mt][nt], a[mt], bf);
                }
        }
        __syncthreads();
        if (it + 2 < nch)
            load_chunk32(sbase + (uint32_t)p * STAGE_B, tid,
                         Ah, Al, i0, Bh, Bl, j0, ld, (it + 2) * 32);
    }

    if (mode == 0) {
        float* Sb = &g_S[b][0][0];
        const float scale = 0.015625f;       // 4096^-0.5
        #pragma unroll
        for (int mt = 0; mt < 4; mt++) {
            int r0 = i0 + wm + mt * 16 + g;
            #pragma unroll
            for (int nt = 0; nt < 4; nt++) {
                int col = j0 + wn + nt * 8 + t * 2;
                float2 lo = make_float2(acc[mt][nt][0] * scale, acc[mt][nt][1] * scale);
                float2 hi = make_float2(acc[mt][nt][2] * scale, acc[mt][nt][3] * scale);
                *(float2*)&Sb[(size_t)r0 * TOK + col]       = lo;
                *(float2*)&Sb[(size_t)(r0 + 8) * TOK + col] = hi;
            }
        }
    } else {
        #pragma unroll
        for (int mt = 0; mt < 4; mt++) {
            #pragma unroll
            for (int rr = 0; rr < 2; rr++) {
                int i   = i0 + wm + mt * 16 + g + rr * 8;
                int img = b * 16 + (i >> 6);
                int gh  = (i >> 3) & 7;
                int gw  = i & 7;
                #pragma unroll
                for (int nt = 0; nt < 4; nt++) {
                    int d  = j0 + wn + nt * 8 + t * 2;
                    int oc = d >> 6;
                    int pi = (d >> 3) & 7;
                    int pj = d & 7;
                    float2 o = make_float2(acc[mt][nt][rr * 2], acc[mt][nt][rr * 2 + 1]);
                    *(float2*)&g_feat[img][oc][gh * 8 + pi][gw * 8 + pj] = o;
                }
            }
        }
    }
}

// ---------------- kernel 3: row softmax, writes P hi/lo bf16 -------------------
__global__ __launch_bounds__(128) void softmax_kernel() {
    const int row = blockIdx.x;            // 0..4095
    const float* p = &g_S[0][0][0] + (size_t)row * TOK;
    __nv_bfloat16* ph = &g_Ph[0][0][0] + (size_t)row * TOK;
    __nv_bfloat16* pl = &g_Pl[0][0][0] + (size_t)row * TOK;
    const int tid = threadIdx.x;
    float v[8];
    float m = -1e30f;
    #pragma unroll
    for (int i = 0; i < 8; i++) { v[i] = p[tid + (i << 7)]; m = fmaxf(m, v[i]); }
    #pragma unroll
    for (int o = 16; o > 0; o >>= 1) m = fmaxf(m, __shfl_xor_sync(0xffffffffu, m, o));
    __shared__ float redm[4], reds[4];
    if ((tid & 31) == 0) redm[tid >> 5] = m;
    __syncthreads();
    m = fmaxf(fmaxf(redm[0], redm[1]), fmaxf(redm[2], redm[3]));
    float sum = 0.f;
    #pragma unroll
    for (int i = 0; i < 8; i++) { v[i] = __expf(v[i] - m); sum += v[i]; }
    #pragma unroll
    for (int o = 16; o > 0; o >>= 1) sum += __shfl_xor_sync(0xffffffffu, sum, o);
    if ((tid & 31) == 0) reds[tid >> 5] = sum;
    __syncthreads();
    sum = reds[0] + reds[1] + reds[2] + reds[3];
    float inv = 1.0f / sum;
    #pragma unroll
    for (int i = 0; i < 8; i++) {
        float pv = v[i] * inv;
        __nv_bfloat16 h = __float2bfloat16(pv);
        ph[tid + (i << 7)] = h;
        pl[tid + (i << 7)] = __float2bfloat16(pv - __bfloat162float(h));
    }
}

// ---------------- launcher ----------------------------------------------------
extern "C" void kernel_launch(void* const* d_in, const int* in_sizes, int n_in,
                              void* d_out, int out_size) {
    (void)in_sizes; (void)n_in; (void)out_size;
    const float* x  = (const float*)d_in[0];
    const float* qw = (const float*)d_in[1];
    const float* qb = (const float*)d_in[2];
    const float* kw = (const float*)d_in[3];
    const float* kb = (const float*)d_in[4];
    const float* vw = (const float*)d_in[5];
    const float* vb = (const float*)d_in[6];
    const float* cw = (const float*)d_in[7];
    const float* cb = (const float*)d_in[8];
    float* out = (float*)d_out;

    const int gsmem = 2 * (int)STAGE_B;               // 81,920 B
    cudaFuncSetAttribute(conv_gemm_kernel, cudaFuncAttributeMaxDynamicSharedMemorySize, CG_SMEM);
    cudaFuncSetAttribute(gemm_mma_kernel,  cudaFuncAttributeMaxDynamicSharedMemorySize, gsmem);

    prep_w_kernel<<<(9 * 64 * 64 + 255) / 256, 256>>>(vw, cw);
    conv_gemm_kernel<<<dim3(64, 8), 512, CG_SMEM>>>(0, x, qw, qb, kw, kb, vb, nullptr);
    transposeV_kernel<<<dim3(DIMD / 32, TOK / 32, NB), 256>>>();
    gemm_mma_kernel<<<dim3(8, 8, NB), 256, gsmem>>>(0);    // S = QK^T * scale
    softmax_kernel<<<NB * TOK, 128>>>();
    gemm_mma_kernel<<<dim3(32, 8, NB), 256, gsmem>>>(1);   // feat = fold(P V)
    conv_gemm_kernel<<<dim3(64, 8), 512, CG_SMEM>>>(1, x, nullptr, nullptr,
                                                    nullptr, nullptr, cb, out);
}

// round 8
// speedup vs baseline: 1.7708x; 1.0551x over previous
#include <cuda_runtime.h>
#include <cuda_bf16.h>
#include <cstdint>

#define NFC   64
#define HWS   64
#define PSZ   8
#define NB    4
#define NT    16
#define NIMG  64      // NB*NT
#define TOK   1024    // NT * 64 patches
#define DIMD  4096    // NFC * PSZ * PSZ

// ---------------- scratch (static device globals; no allocation) -------------
__device__ __align__(128) __nv_bfloat16 g_Qh[NB][TOK][DIMD];
__device__ __align__(128) __nv_bfloat16 g_Ql[NB][TOK][DIMD];
__device__ __align__(128) __nv_bfloat16 g_Kh[NB][TOK][DIMD];
__device__ __align__(128) __nv_bfloat16 g_Kl[NB][TOK][DIMD];
__device__ __align__(128) __nv_bfloat16 g_Vth[NB][DIMD][TOK];
__device__ __align__(128) __nv_bfloat16 g_Vtl[NB][DIMD][TOK];
__device__ __align__(128) float         g_S [NB][TOK][TOK];
__device__ __align__(128) __nv_bfloat16 g_Ph[NB][TOK][TOK];
__device__ __align__(128) __nv_bfloat16 g_Pl[NB][TOK][TOK];
__device__ __align__(128) float g_feat[NIMG][NFC][HWS][HWS];
// conv weights as [tap][oc][ic] bf16 hi/lo, pre-swizzled for ldmatrix
__device__ __align__(128) __nv_bfloat16 g_Wvh[9 * 4096];
__device__ __align__(128) __nv_bfloat16 g_Wvl[9 * 4096];
__device__ __align__(128) __nv_bfloat16 g_Wch[9 * 4096];
__device__ __align__(128) __nv_bfloat16 g_Wcl[9 * 4096];

// ======================= helpers ==============================================
__device__ __forceinline__ uint32_t smem_u32(const void* p) {
    uint32_t a;
    asm("{ .reg .u64 t; cvta.to.shared.u64 t, %1; cvt.u32.u64 %0, t; }"
        : "=r"(a) : "l"(p));
    return a;
}
__device__ __forceinline__ void cpa16(uint32_t dst, const void* src) {
    asm volatile("cp.async.cg.shared.global [%0], [%1], 16;"
                 :: "r"(dst), "l"(__cvta_generic_to_global(src)));
}
__device__ __forceinline__ void cpa_commit() { asm volatile("cp.async.commit_group;" ::: "memory"); }
__device__ __forceinline__ void cpa_wait1()  { asm volatile("cp.async.wait_group 1;" ::: "memory"); }
__device__ __forceinline__ void cpa_wait0()  { asm volatile("cp.async.wait_group 0;" ::: "memory"); }

__device__ __forceinline__ void mma16816(float* c, const uint32_t* a, const uint32_t* b) {
    asm volatile(
        "mma.sync.aligned.m16n8k16.row.col.f32.bf16.bf16.f32 "
        "{%0,%1,%2,%3}, {%4,%5,%6,%7}, {%8,%9}, {%0,%1,%2,%3};"
        : "+f"(c[0]), "+f"(c[1]), "+f"(c[2]), "+f"(c[3])
        : "r"(a[0]), "r"(a[1]), "r"(a[2]), "r"(a[3]), "r"(b[0]), "r"(b[1]));
}
__device__ __forceinline__ void ldsm4(uint32_t* r, uint32_t addr) {
    asm volatile("ldmatrix.sync.aligned.m8n8.x4.shared.b16 {%0,%1,%2,%3}, [%4];"
                 : "=r"(r[0]), "=r"(r[1]), "=r"(r[2]), "=r"(r[3]) : "r"(addr));
}

// ---------------- kernel 0: prep conv weights (hi/lo, swizzled) ---------------
__global__ void prep_w_kernel(const float* __restrict__ vw,
                              const float* __restrict__ cw) {
    int idx = blockIdx.x * blockDim.x + threadIdx.x;
    if (idx < 9 * 64 * 64) {
        int t   = idx >> 12;
        int rem = idx & 4095;
        int oc  = rem >> 6;
        int ic  = rem & 63;
        int di  = t * 4096 + oc * 64 + (ic ^ ((oc & 7) << 3));
        float v = vw[oc * 576 + ic * 9 + t];
        __nv_bfloat16 h = __float2bfloat16(v);
        g_Wvh[di] = h;
        g_Wvl[di] = __float2bfloat16(v - __bfloat162float(h));
        v = cw[oc * 576 + ic * 9 + t];
        h = __float2bfloat16(v);
        g_Wch[di] = h;
        g_Wcl[di] = __float2bfloat16(v - __bfloat162float(h));
    }
}

// ---------------- kernel: depthwise q/k conv -> token-layout hi/lo bf16 -------
__global__ __launch_bounds__(512) void dwqk_kernel(
    const float* __restrict__ x,
    const float* __restrict__ qw, const float* __restrict__ qb,
    const float* __restrict__ kw, const float* __restrict__ kb)
{
    extern __shared__ float s[];          // [64][10][66]
    const int img   = blockIdx.x;
    const int ytile = blockIdx.y;
    const int y0    = ytile * 8;
    const int bb    = img >> 4;
    const int tt    = img & 15;
    const int tid   = threadIdx.x;
    const float* xim = x + (size_t)img * NFC * HWS * HWS;

    for (int idx = tid; idx < 64 * 10 * 66; idx += 512) {
        int c  = idx / 660;
        int rr = idx - c * 660;
        int yy = rr / 66;
        int xx = rr - yy * 66;
        int gy = y0 - 1 + yy;
        int gx = xx - 1;
        float v = 0.f;
        if (gy >= 0 && gy < 64 && gx >= 0 && gx < 64)
            v = xim[c * 4096 + gy * 64 + gx];
        s[idx] = v;
    }
    __syncthreads();

    const int c  = tid >> 3;
    const int xb = tid & 7;
    const int x0 = xb * 8;
    const int tok = tt * 64 + ytile * 8 + xb;
    float wq[9], wk[9];
    #pragma unroll
    for (int i = 0; i < 9; i++) { wq[i] = qw[c * 9 + i]; wk[i] = kw[c * 9 + i]; }
    const float bq = qb[c], bk = kb[c];
    const float* sc = s + c * 660;

    #pragma unroll
    for (int y = 0; y < 8; y++) {
        float r0[10], r1[10], r2[10];
        #pragma unroll
        for (int j = 0; j < 10; j++) {
            r0[j] = sc[(y + 0) * 66 + x0 + j];
            r1[j] = sc[(y + 1) * 66 + x0 + j];
            r2[j] = sc[(y + 2) * 66 + x0 + j];
        }
        uint32_t qh4[4], ql4[4], kh4[4], kl4[4];
        #pragma unroll
        for (int pp = 0; pp < 4; pp++) {
            float aq[2], ak[2];
            #pragma unroll
            for (int e = 0; e < 2; e++) {
                int xx = pp * 2 + e;
                float q = bq, k = bk;
                #pragma unroll
                for (int kx = 0; kx < 3; kx++) {
                    q = fmaf(r0[xx + kx], wq[kx], q);
                    q = fmaf(r1[xx + kx], wq[3 + kx], q);
                    q = fmaf(r2[xx + kx], wq[6 + kx], q);
                    k = fmaf(r0[xx + kx], wk[kx], k);
                    k = fmaf(r1[xx + kx], wk[3 + kx], k);
                    k = fmaf(r2[xx + kx], wk[6 + kx], k);
                }
                aq[e] = q; ak[e] = k;
            }
            __nv_bfloat162 h2 = __floats2bfloat162_rn(aq[0], aq[1]);
            qh4[pp] = *(uint32_t*)&h2;
            __nv_bfloat162 l2 = __floats2bfloat162_rn(
                aq[0] - __bfloat162float(__low2bfloat16(h2)),
                aq[1] - __bfloat162float(__high2bfloat16(h2)));
            ql4[pp] = *(uint32_t*)&l2;
            h2 = __floats2bfloat162_rn(ak[0], ak[1]);
            kh4[pp] = *(uint32_t*)&h2;
            l2 = __floats2bfloat162_rn(
                ak[0] - __bfloat162float(__low2bfloat16(h2)),
                ak[1] - __bfloat162float(__high2bfloat16(h2)));
            kl4[pp] = *(uint32_t*)&l2;
        }
        const int d = c * 64 + y * 8;
        *(uint4*)&g_Qh[bb][tok][d] = make_uint4(qh4[0], qh4[1], qh4[2], qh4[3]);
        *(uint4*)&g_Ql[bb][tok][d] = make_uint4(ql4[0], ql4[1], ql4[2], ql4[3]);
        *(uint4*)&g_Kh[bb][tok][d] = make_uint4(kh4[0], kh4[1], kh4[2], kh4[3]);
        *(uint4*)&g_Kl[bb][tok][d] = make_uint4(kl4[0], kl4[1], kl4[2], kl4[3]);
    }
}

// ---------------- implicit-GEMM conv (tensor cores), both convs ---------------
// mode 0 (V): src = x image; writes Vt hi/lo (transposed, +vb)
// mode 1 (C): src = g_feat; writes out = conv + cb + residual x
#define CG_XH    0u
#define CG_XL    84480u
#define CG_W     168960u       // + stage*16384 ; hi at +0, lo at +8192
#define CG_SMEM  201728
#define DB_PITCH 520

__global__ __launch_bounds__(512) void conv_gemm_kernel(
    int mode,
    const float* __restrict__ xin,
    const float* __restrict__ bias,
    float* __restrict__ out)
{
    extern __shared__ char sm[];
    const uint32_t sb = smem_u32(sm);
    const int img   = blockIdx.x;
    const int ytile = blockIdx.y;
    const int y0    = ytile * 8;
    const int tid   = threadIdx.x;
    const int wid   = tid >> 5;
    const int lane  = tid & 31;
    const int lrow  = lane & 15;
    const int lhi   = lane >> 4;
    const int wy    = wid >> 1;          // warp y-row (0..7)
    const int wx0   = (wid & 1) * 32;    // warp x base

    const float* src = (mode == 0) ? (xin + (size_t)img * NFC * HWS * HWS)
                                   : &g_feat[img][0][0][0];
    const __nv_bfloat16* Wh = (mode == 0) ? g_Wvh : g_Wch;
    const __nv_bfloat16* Wl = (mode == 0) ? g_Wvl : g_Wcl;

    // prefetch weight taps 0,1 (cp.async groups)
    #pragma unroll
    for (int s = 0; s < 2; s++) {
        for (int u = tid; u < 1024; u += 512) {
            int term = u >> 9, off = (u & 511) * 16;
            const char* gsrc = (const char*)((term ? Wl : Wh) + s * 4096) + off;
            cpa16(sb + CG_W + (uint32_t)s * 16384u + (uint32_t)(term * 8192 + off), gsrc);
        }
        cpa_commit();
    }

    // load X halo tile -> bf16 hi/lo swizzled [r][c]
    for (int base = 0; base < 42240; base += 512) {
        int idx = base + tid;
        if (idx < 42240) {
            int c  = idx / 660;
            int r  = idx - c * 660;
            int yy = r / 66;
            int xx = r - yy * 66;
            int gy = y0 - 1 + yy, gx = xx - 1;
            float v = 0.f;
            if (gy >= 0 && gy < 64 && gx >= 0 && gx < 64)
                v = src[c * 4096 + gy * 64 + gx];
            __nv_bfloat16 h = __float2bfloat16(v);
            __nv_bfloat16 l = __float2bfloat16(v - __bfloat162float(h));
            uint32_t o = (uint32_t)(r * 128 + 2 * (c ^ ((r & 7) << 3)));
            *(__nv_bfloat16*)(sm + CG_XH + o) = h;
            *(__nv_bfloat16*)(sm + CG_XL + o) = l;
        }
    }
    __syncthreads();

    // ---- main MMA loop over 9 taps ----
    float acc[2][8][4];
    #pragma unroll
    for (int mt = 0; mt < 2; mt++)
        #pragma unroll
        for (int nt = 0; nt < 8; nt++)
            #pragma unroll
            for (int q = 0; q < 4; q++) acc[mt][nt][q] = 0.f;

    for (int tap = 0; tap < 9; tap++) {
        const int ky = tap / 3;
        const int kx = tap - ky * 3;
        if (tap + 1 < 9) cpa_wait1(); else cpa_wait0();
        __syncthreads();
        const uint32_t wbuf = sb + CG_W + (uint32_t)(tap & 1) * 16384u;
        const int rbase = (wy + ky) * 66 + wx0 + lrow + kx;

        #pragma unroll
        for (int ks = 0; ks < 4; ks++) {
            const uint32_t cofs = (uint32_t)(ks * 32 + lhi * 16);
            uint32_t a[2][4], bh[4][4], bl[4][4];
            #pragma unroll
            for (int mt = 0; mt < 2; mt++) {
                int r = rbase + mt * 16;
                ldsm4(a[mt], sb + CG_XH + (uint32_t)(r * 128)
                             + (cofs ^ ((uint32_t)(r & 7) << 4)));
            }
            #pragma unroll
            for (int np = 0; np < 4; np++) {
                int o = np * 16 + lrow;
                ldsm4(bh[np], wbuf + (uint32_t)(o * 128)
                              + (cofs ^ ((uint32_t)(o & 7) << 4)));
            }
            #pragma unroll
            for (int mt = 0; mt < 2; mt++)
                #pragma unroll
                for (int nt = 0; nt < 8; nt++) {
                    uint32_t bf[2] = { bh[nt >> 1][nt & 1], bh[nt >> 1][(nt & 1) + 2] };
                    mma16816(acc[mt][nt], a[mt], bf);
                }
            #pragma unroll
            for (int np = 0; np < 4; np++) {
                int o = np * 16 + lrow;
                ldsm4(bl[np], wbuf + 8192u + (uint32_t)(o * 128)
                              + (cofs ^ ((uint32_t)(o & 7) << 4)));
            }
            #pragma unroll
            for (int mt = 0; mt < 2; mt++)
                #pragma unroll
                for (int nt = 0; nt < 8; nt++) {
                    uint32_t bf[2] = { bl[nt >> 1][nt & 1], bl[nt >> 1][(nt & 1) + 2] };
                    mma16816(acc[mt][nt], a[mt], bf);
                }
            #pragma unroll
            for (int mt = 0; mt < 2; mt++) {
                int r = rbase + mt * 16;
                ldsm4(a[mt], sb + CG_XL + (uint32_t)(r * 128)
                             + (cofs ^ ((uint32_t)(r & 7) << 4)));
            }
            #pragma unroll
            for (int mt = 0; mt < 2; mt++)
                #pragma unroll
                for (int nt = 0; nt < 8; nt++) {
                    uint32_t bf[2] = { bh[nt >> 1][nt & 1], bh[nt >> 1][(nt & 1) + 2] };
                    mma16816(acc[mt][nt], a[mt], bf);
                }
        }
        __syncthreads();
        if (tap + 2 < 9) {
            const int tp = tap + 2;
            const uint32_t dbuf = sb + CG_W + (uint32_t)(tp & 1) * 16384u;
            for (int u = tid; u < 1024; u += 512) {
                int term = u >> 9, off = (u & 511) * 16;
                const char* gsrc = (const char*)((term ? Wl : Wh) + tp * 4096) + off;
                cpa16(dbuf + (uint32_t)(term * 8192 + off), gsrc);
            }
            cpa_commit();
        }
    }

    // ---- stage D through smem (X area is dead now), then coalesced writeout ---
    float* Dbuf = (float*)sm;
    const int g  = lane >> 2;
    const int tq = lane & 3;
    #pragma unroll
    for (int mt = 0; mt < 2; mt++)
        #pragma unroll
        for (int rr = 0; rr < 2; rr++) {
            int px = wy * 64 + wx0 + mt * 16 + g + rr * 8;
            #pragma unroll
            for (int nt = 0; nt < 8; nt++) {
                int oc = nt * 8 + tq * 2;
                Dbuf[oc * DB_PITCH + px]       = acc[mt][nt][rr * 2];
                Dbuf[(oc + 1) * DB_PITCH + px] = acc[mt][nt][rr * 2 + 1];
            }
        }
    __syncthreads();

    if (mode == 0) {
        // fused transpose + hi/lo split: write Vt[d][tok] directly
        const int bb = img >> 4, tt = img & 15;
        const int tokbase = tt * 64 + ytile * 8;
        for (int e = tid; e < 32768; e += 512) {
            int d  = e >> 3, xb = e & 7;
            int oc = d >> 6, y = (d >> 3) & 7, xa = d & 7;
            float v = Dbuf[oc * DB_PITCH + y * 64 + xb * 8 + xa] + bias[oc];
            __nv_bfloat16 h = __float2bfloat16(v);
            g_Vth[bb][d][tokbase + xb] = h;
            g_Vtl[bb][d][tokbase + xb] = __float2bfloat16(v - __bfloat162float(h));
        }
    } else {
        for (int e = tid; e < 32768; e += 512) {
            int oc = e >> 9, y = (e >> 6) & 7, xx = e & 63;
            int gb = ((img * 64 + oc) * 64 + y0 + y) * 64 + xx;
            out[gb] = Dbuf[oc * DB_PITCH + y * 64 + xx] + bias[oc] + xin[gb];
        }
    }
}

// ---------------- mma.sync GEMM (both attention GEMMs) -------------------------
// CTA tile 64x128, 4 warps (warp tile 64x32), K-chunk 32, 3 CTAs/SM.
#define OFF_AH   0u
#define OFF_AL   5120u                  // 64*80
#define OFF_BH   10240u
#define OFF_BL   20480u
#define STAGE_B  30720u

__device__ __forceinline__ void load_chunk32(
    uint32_t sb, int tid,
    const __nv_bfloat16* Ah, const __nv_bfloat16* Al, int i0,
    const __nv_bfloat16* Bh, const __nv_bfloat16* Bl, int j0,
    int ld, int k0)
{
    #pragma unroll
    for (int u = tid; u < 1536; u += 128) {
        const __nv_bfloat16* src;
        uint32_t dst;
        if (u < 512) {                   // A hi/lo: 64 rows each
            int term = u >> 8, idx = u & 255;
            int r = idx >> 2, c = idx & 3;
            src = (term ? Al : Ah) + (size_t)(i0 + r) * ld + k0 + c * 8;
            dst = sb + (uint32_t)term * 5120u + (uint32_t)(r * 80 + c * 16);
        } else {                         // B hi/lo: 128 rows each
            int v = u - 512;
            int term = v >> 9, idx = v & 511;
            int r = idx >> 2, c = idx & 3;
            src = (term ? Bl : Bh) + (size_t)(j0 + r) * ld + k0 + c * 8;
            dst = sb + 10240u + (uint32_t)term * 10240u + (uint32_t)(r * 80 + c * 16);
        }
        cpa16(dst, src);
    }
    cpa_commit();
}

__global__ __launch_bounds__(128, 3) void gemm_mma_kernel(int mode)
{
    extern __shared__ char dsm[];
    const int tid  = threadIdx.x;
    const int wid  = tid >> 5;
    const int lane = tid & 31;
    const int g    = lane >> 2;          // 0..7
    const int t    = lane & 3;           // 0..3
    const int b    = blockIdx.z;
    const int i0   = blockIdx.y * 64;
    const int j0   = blockIdx.x * 128;
    const int wn   = wid * 32;           // warp col base
    const int lrow = lane & 15;
    const int lk   = (lane >> 4) << 3;

    const __nv_bfloat16 *Ah, *Al, *Bh, *Bl;
    int ld, nch;
    if (mode == 0) {
        Ah = &g_Qh[b][0][0]; Al = &g_Ql[b][0][0];
        Bh = &g_Kh[b][0][0]; Bl = &g_Kl[b][0][0];
        ld = DIMD; nch = DIMD / 32;
    } else {
        Ah = &g_Ph[b][0][0]; Al = &g_Pl[b][0][0];
        Bh = &g_Vth[b][0][0]; Bl = &g_Vtl[b][0][0];
        ld = TOK; nch = TOK / 32;
    }

    const uint32_t sbase = smem_u32(dsm);
    float acc[4][4][4];
    #pragma unroll
    for (int mt = 0; mt < 4; mt++)
        #pragma unroll
        for (int nt = 0; nt < 4; nt++)
            #pragma unroll
            for (int q = 0; q < 4; q++) acc[mt][nt][q] = 0.f;

    load_chunk32(sbase,           tid, Ah, Al, i0, Bh, Bl, j0, ld, 0);
    load_chunk32(sbase + STAGE_B, tid, Ah, Al, i0, Bh, Bl, j0, ld, 32);

    for (int it = 0; it < nch; ++it) {
        const int p = it & 1;
        const uint32_t st = sbase + (uint32_t)p * STAGE_B;
        if (it + 1 < nch) cpa_wait1(); else cpa_wait0();
        __syncthreads();

        #pragma unroll
        for (int ks = 0; ks < 32; ks += 16) {
            uint32_t a[4][4], bh2[2][4], bl2[2][4];
            const uint32_t cofs = (uint32_t)((ks + lk) * 2);
            #pragma unroll
            for (int mt = 0; mt < 4; mt++)
                ldsm4(a[mt], st + OFF_AH + (uint32_t)((mt * 16 + lrow) * 80) + cofs);
            #pragma unroll
            for (int ntp = 0; ntp < 2; ntp++)
                ldsm4(bh2[ntp], st + OFF_BH + (uint32_t)((wn + ntp * 16 + lrow) * 80) + cofs);
            #pragma unroll
            for (int mt = 0; mt < 4; mt++)
                #pragma unroll
                for (int nt = 0; nt < 4; nt++) {
                    uint32_t bf[2] = { bh2[nt >> 1][nt & 1], bh2[nt >> 1][(nt & 1) + 2] };
                    mma16816(acc[mt][nt], a[mt], bf);
                }
            #pragma unroll
            for (int ntp = 0; ntp < 2; ntp++)
                ldsm4(bl2[ntp], st + OFF_BL + (uint32_t)((wn + ntp * 16 + lrow) * 80) + cofs);
            #pragma unroll
            for (int mt = 0; mt < 4; mt++)
                #pragma unroll
                for (int nt = 0; nt < 4; nt++) {
                    uint32_t bf[2] = { bl2[nt >> 1][nt & 1], bl2[nt >> 1][(nt & 1) + 2] };
                    mma16816(acc[mt][nt], a[mt], bf);
                }
            #pragma unroll
            for (int mt = 0; mt < 4; mt++)
                ldsm4(a[mt], st + OFF_AL + (uint32_t)((mt * 16 + lrow) * 80) + cofs);
            #pragma unroll
            for (int mt = 0; mt < 4; mt++)
                #pragma unroll
                for (int nt = 0; nt < 4; nt++) {
                    uint32_t bf[2] = { bh2[nt >> 1][nt & 1], bh2[nt >> 1][(nt & 1) + 2] };
                    mma16816(acc[mt][nt], a[mt], bf);
                }
        }
        __syncthreads();
        if (it + 2 < nch)
            load_chunk32(sbase + (uint32_t)p * STAGE_B, tid,
                         Ah, Al, i0, Bh, Bl, j0, ld, (it + 2) * 32);
    }

    if (mode == 0) {
        float* Sb = &g_S[b][0][0];
        const float scale = 0.015625f;       // 4096^-0.5
        #pragma unroll
        for (int mt = 0; mt < 4; mt++) {
            int r0 = i0 + mt * 16 + g;
            #pragma unroll
            for (int nt = 0; nt < 4; nt++) {
                int col = j0 + wn + nt * 8 + t * 2;
                float2 lo = make_float2(acc[mt][nt][0] * scale, acc[mt][nt][1] * scale);
                float2 hi = make_float2(acc[mt][nt][2] * scale, acc[mt][nt][3] * scale);
                *(float2*)&Sb[(size_t)r0 * TOK + col]       = lo;
                *(float2*)&Sb[(size_t)(r0 + 8) * TOK + col] = hi;
            }
        }
    } else {
        #pragma unroll
        for (int mt = 0; mt < 4; mt++) {
            #pragma unroll
            for (int rr = 0; rr < 2; rr++) {
                int i   = i0 + mt * 16 + g + rr * 8;
                int img = b * 16 + (i >> 6);
                int gh  = (i >> 3) & 7;
                int gw  = i & 7;
                #pragma unroll
                for (int nt = 0; nt < 4; nt++) {
                    int d  = j0 + wn + nt * 8 + t * 2;
                    int oc = d >> 6;
                    int pi = (d >> 3) & 7;
                    int pj = d & 7;
                    float2 o = make_float2(acc[mt][nt][rr * 2], acc[mt][nt][rr * 2 + 1]);
                    *(float2*)&g_feat[img][oc][gh * 8 + pi][gw * 8 + pj] = o;
                }
            }
        }
    }
}

// ---------------- kernel: row softmax, writes P hi/lo bf16 ---------------------
__global__ __launch_bounds__(128) void softmax_kernel() {
    const int row = blockIdx.x;            // 0..4095
    const float* p = &g_S[0][0][0] + (size_t)row * TOK;
    __nv_bfloat16* ph = &g_Ph[0][0][0] + (size_t)row * TOK;
    __nv_bfloat16* pl = &g_Pl[0][0][0] + (size_t)row * TOK;
    const int tid = threadIdx.x;
    float v[8];
    float m = -1e30f;
    #pragma unroll
    for (int i = 0; i < 8; i++) { v[i] = p[tid + (i << 7)]; m = fmaxf(m, v[i]); }
    #pragma unroll
    for (int o = 16; o > 0; o >>= 1) m = fmaxf(m, __shfl_xor_sync(0xffffffffu, m, o));
    __shared__ float redm[4], reds[4];
    if ((tid & 31) == 0) redm[tid >> 5] = m;
    __syncthreads();
    m = fmaxf(fmaxf(redm[0], redm[1]), fmaxf(redm[2], redm[3]));
    float sum = 0.f;
    #pragma unroll
    for (int i = 0; i < 8; i++) { v[i] = __expf(v[i] - m); sum += v[i]; }
    #pragma unroll
    for (int o = 16; o > 0; o >>= 1) sum += __shfl_xor_sync(0xffffffffu, sum, o);
    if ((tid & 31) == 0) reds[tid >> 5] = sum;
    __syncthreads();
    sum = reds[0] + reds[1] + reds[2] + reds[3];
    float inv = 1.0f / sum;
    #pragma unroll
    for (int i = 0; i < 8; i++) {
        float pv = v[i] * inv;
        __nv_bfloat16 h = __float2bfloat16(pv);
        ph[tid + (i << 7)] = h;
        pl[tid + (i << 7)] = __float2bfloat16(pv - __bfloat162float(h));
    }
}

// ---------------- launcher ----------------------------------------------------
extern "C" void kernel_launch(void* const* d_in, const int* in_sizes, int n_in,
                              void* d_out, int out_size) {
    (void)in_sizes; (void)n_in; (void)out_size;
    const float* x  = (const float*)d_in[0];
    const float* qw = (const float*)d_in[1];
    const float* qb = (const float*)d_in[2];
    const float* kw = (const float*)d_in[3];
    const float* kb = (const float*)d_in[4];
    const float* vw = (const float*)d_in[5];
    const float* vb = (const float*)d_in[6];
    const float* cw = (const float*)d_in[7];
    const float* cb = (const float*)d_in[8];
    float* out = (float*)d_out;

    const int dsmem = 64 * 10 * 66 * sizeof(float);   // 168,960 B
    const int gsmem = 2 * (int)STAGE_B;               // 61,440 B
    cudaFuncSetAttribute(dwqk_kernel,      cudaFuncAttributeMaxDynamicSharedMemorySize, dsmem);
    cudaFuncSetAttribute(conv_gemm_kernel, cudaFuncAttributeMaxDynamicSharedMemorySize, CG_SMEM);
    cudaFuncSetAttribute(gemm_mma_kernel,  cudaFuncAttributeMaxDynamicSharedMemorySize, gsmem);

    prep_w_kernel<<<(9 * 64 * 64 + 255) / 256, 256>>>(vw, cw);
    dwqk_kernel<<<dim3(64, 8), 512, dsmem>>>(x, qw, qb, kw, kb);
    conv_gemm_kernel<<<dim3(64, 8), 512, CG_SMEM>>>(0, x, vb, nullptr);
    gemm_mma_kernel<<<dim3(8, 16, NB), 128, gsmem>>>(0);    // S = QK^T * scale
    softmax_kernel<<<NB * TOK, 128>>>();
    gemm_mma_kernel<<<dim3(32, 16, NB), 128, gsmem>>>(1);   // feat = fold(P V)
    conv_gemm_kernel<<<dim3(64, 8), 512, CG_SMEM>>>(1, x, cb, out);
}

// round 10
// speedup vs baseline: 1.8717x; 1.0570x over previous
#include <cuda_runtime.h>
#include <cuda_bf16.h>
#include <cstdint>

#define NFC   64
#define HWS   64
#define PSZ   8
#define NB    4
#define NT    16
#define NIMG  64      // NB*NT
#define TOK   1024    // NT * 64 patches
#define DIMD  4096    // NFC * PSZ * PSZ

// ---------------- scratch (static device globals; no allocation) -------------
__device__ __align__(128) __nv_bfloat16 g_Qh[NB][TOK][DIMD];
__device__ __align__(128) __nv_bfloat16 g_Ql[NB][TOK][DIMD];
__device__ __align__(128) __nv_bfloat16 g_Kh[NB][TOK][DIMD];
__device__ __align__(128) __nv_bfloat16 g_Kl[NB][TOK][DIMD];
__device__ __align__(128) __nv_bfloat16 g_Vth[NB][DIMD][TOK];
__device__ __align__(128) __nv_bfloat16 g_Vtl[NB][DIMD][TOK];
__device__ __align__(128) float         g_S [NB][TOK][TOK];
__device__ __align__(128) __nv_bfloat16 g_Ph[NB][TOK][TOK];
__device__ __align__(128) __nv_bfloat16 g_Pl[NB][TOK][TOK];
__device__ __align__(128) float g_feat[NIMG][NFC][HWS][HWS];
// conv weights as [tap][oc][ic] bf16 hi/lo, pre-swizzled for ldmatrix
__device__ __align__(128) __nv_bfloat16 g_Wvh[9 * 4096];
__device__ __align__(128) __nv_bfloat16 g_Wvl[9 * 4096];
__device__ __align__(128) __nv_bfloat16 g_Wch[9 * 4096];
__device__ __align__(128) __nv_bfloat16 g_Wcl[9 * 4096];

// ---------------- side stream + events (created once, before main) -----------
struct SideStream {
    cudaStream_t s1;
    cudaEvent_t  e0, e1;
    SideStream() {
        cudaStreamCreateWithFlags(&s1, cudaStreamNonBlocking);
        cudaEventCreateWithFlags(&e0, cudaEventDisableTiming);
        cudaEventCreateWithFlags(&e1, cudaEventDisableTiming);
    }
};
static SideStream g_ss;

// ======================= helpers ==============================================
__device__ __forceinline__ uint32_t smem_u32(const void* p) {
    uint32_t a;
    asm("{ .reg .u64 t; cvta.to.shared.u64 t, %1; cvt.u32.u64 %0, t; }"
        : "=r"(a) : "l"(p));
    return a;
}
__device__ __forceinline__ void cpa16(uint32_t dst, const void* src) {
    asm volatile("cp.async.cg.shared.global [%0], [%1], 16;"
                 :: "r"(dst), "l"(__cvta_generic_to_global(src)));
}
__device__ __forceinline__ void cpa_commit() { asm volatile("cp.async.commit_group;" ::: "memory"); }
__device__ __forceinline__ void cpa_wait1()  { asm volatile("cp.async.wait_group 1;" ::: "memory"); }
__device__ __forceinline__ void cpa_wait0()  { asm volatile("cp.async.wait_group 0;" ::: "memory"); }

__device__ __forceinline__ void mma16816(float* c, const uint32_t* a, const uint32_t* b) {
    asm volatile(
        "mma.sync.aligned.m16n8k16.row.col.f32.bf16.bf16.f32 "
        "{%0,%1,%2,%3}, {%4,%5,%6,%7}, {%8,%9}, {%0,%1,%2,%3};"
        : "+f"(c[0]), "+f"(c[1]), "+f"(c[2]), "+f"(c[3])
        : "r"(a[0]), "r"(a[1]), "r"(a[2]), "r"(a[3]), "r"(b[0]), "r"(b[1]));
}
__device__ __forceinline__ void ldsm4(uint32_t* r, uint32_t addr) {
    asm volatile("ldmatrix.sync.aligned.m8n8.x4.shared.b16 {%0,%1,%2,%3}, [%4];"
                 : "=r"(r[0]), "=r"(r[1]), "=r"(r[2]), "=r"(r[3]) : "r"(addr));
}

// ---------------- kernel 0: prep conv weights (hi/lo, swizzled) ---------------
__global__ void prep_w_kernel(const float* __restrict__ vw,
                              const float* __restrict__ cw) {
    int idx = blockIdx.x * blockDim.x + threadIdx.x;
    if (idx < 9 * 64 * 64) {
        int t   = idx >> 12;
        int rem = idx & 4095;
        int oc  = rem >> 6;
        int ic  = rem & 63;
        int di  = t * 4096 + oc * 64 + (ic ^ ((oc & 7) << 3));
        float v = vw[oc * 576 + ic * 9 + t];
        __nv_bfloat16 h = __float2bfloat16(v);
        g_Wvh[di] = h;
        g_Wvl[di] = __float2bfloat16(v - __bfloat162float(h));
        v = cw[oc * 576 + ic * 9 + t];
        h = __float2bfloat16(v);
        g_Wch[di] = h;
        g_Wcl[di] = __float2bfloat16(v - __bfloat162float(h));
    }
}

// ---------------- kernel: depthwise q/k conv -> token-layout hi/lo bf16 -------
__global__ __launch_bounds__(512) void dwqk_kernel(
    const float* __restrict__ x,
    const float* __restrict__ qw, const float* __restrict__ qb,
    const float* __restrict__ kw, const float* __restrict__ kb)
{
    extern __shared__ float s[];          // [64][10][66]
    const int img   = blockIdx.x;
    const int ytile = blockIdx.y;
    const int y0    = ytile * 8;
    const int bb    = img >> 4;
    const int tt    = img & 15;
    const int tid   = threadIdx.x;
    const float* xim = x + (size_t)img * NFC * HWS * HWS;

    for (int idx = tid; idx < 64 * 10 * 66; idx += 512) {
        int c  = idx / 660;
        int rr = idx - c * 660;
        int yy = rr / 66;
        int xx = rr - yy * 66;
        int gy = y0 - 1 + yy;
        int gx = xx - 1;
        float v = 0.f;
        if (gy >= 0 && gy < 64 && gx >= 0 && gx < 64)
            v = xim[c * 4096 + gy * 64 + gx];
        s[idx] = v;
    }
    __syncthreads();

    const int c  = tid >> 3;
    const int xb = tid & 7;
    const int x0 = xb * 8;
    const int tok = tt * 64 + ytile * 8 + xb;
    float wq[9], wk[9];
    #pragma unroll
    for (int i = 0; i < 9; i++) { wq[i] = qw[c * 9 + i]; wk[i] = kw[c * 9 + i]; }
    const float bq = qb[c], bk = kb[c];
    const float* sc = s + c * 660;

    #pragma unroll
    for (int y = 0; y < 8; y++) {
        float r0[10], r1[10], r2[10];
        #pragma unroll
        for (int j = 0; j < 10; j++) {
            r0[j] = sc[(y + 0) * 66 + x0 + j];
            r1[j] = sc[(y + 1) * 66 + x0 + j];
            r2[j] = sc[(y + 2) * 66 + x0 + j];
        }
        uint32_t qh4[4], ql4[4], kh4[4], kl4[4];
        #pragma unroll
        for (int pp = 0; pp < 4; pp++) {
            float aq[2], ak[2];
            #pragma unroll
            for (int e = 0; e < 2; e++) {
                int xx = pp * 2 + e;
                float q = bq, k = bk;
                #pragma unroll
                for (int kx = 0; kx < 3; kx++) {
                    q = fmaf(r0[xx + kx], wq[kx], q);
                    q = fmaf(r1[xx + kx], wq[3 + kx], q);
                    q = fmaf(r2[xx + kx], wq[6 + kx], q);
                    k = fmaf(r0[xx + kx], wk[kx], k);
                    k = fmaf(r1[xx + kx], wk[3 + kx], k);
                    k = fmaf(r2[xx + kx], wk[6 + kx], k);
                }
                aq[e] = q; ak[e] = k;
            }
            __nv_bfloat162 h2 = __floats2bfloat162_rn(aq[0], aq[1]);
            qh4[pp] = *(uint32_t*)&h2;
            __nv_bfloat162 l2 = __floats2bfloat162_rn(
                aq[0] - __bfloat162float(__low2bfloat16(h2)),
                aq[1] - __bfloat162float(__high2bfloat16(h2)));
            ql4[pp] = *(uint32_t*)&l2;
            h2 = __floats2bfloat162_rn(ak[0], ak[1]);
            kh4[pp] = *(uint32_t*)&h2;
            l2 = __floats2bfloat162_rn(
                ak[0] - __bfloat162float(__low2bfloat16(h2)),
                ak[1] - __bfloat162float(__high2bfloat16(h2)));
            kl4[pp] = *(uint32_t*)&l2;
        }
        const int d = c * 64 + y * 8;
        *(uint4*)&g_Qh[bb][tok][d] = make_uint4(qh4[0], qh4[1], qh4[2], qh4[3]);
        *(uint4*)&g_Ql[bb][tok][d] = make_uint4(ql4[0], ql4[1], ql4[2], ql4[3]);
        *(uint4*)&g_Kh[bb][tok][d] = make_uint4(kh4[0], kh4[1], kh4[2], kh4[3]);
        *(uint4*)&g_Kl[bb][tok][d] = make_uint4(kl4[0], kl4[1], kl4[2], kl4[3]);
    }
}

// ---------------- implicit-GEMM conv (tensor cores), both convs ---------------
// mode 0 (V): src = x image; writes Vt hi/lo (transposed, +vb)
// mode 1 (C): src = g_feat; writes out = conv + cb + residual x
#define CG_XH    0u
#define CG_XL    84480u
#define CG_W     168960u       // + stage*16384 ; hi at +0, lo at +8192
#define CG_SMEM  201728
#define DB_PITCH 520

__global__ __launch_bounds__(512) void conv_gemm_kernel(
    int mode,
    const float* __restrict__ xin,
    const float* __restrict__ bias,
    float* __restrict__ out)
{
    extern __shared__ char sm[];
    const uint32_t sb = smem_u32(sm);
    const int img   = blockIdx.x;
    const int ytile = blockIdx.y;
    const int y0    = ytile * 8;
    const int tid   = threadIdx.x;
    const int wid   = tid >> 5;
    const int lane  = tid & 31;
    const int lrow  = lane & 15;
    const int lhi   = lane >> 4;
    const int wy    = wid >> 1;          // warp y-row (0..7)
    const int wx0   = (wid & 1) * 32;    // warp x base

    const float* src = (mode == 0) ? (xin + (size_t)img * NFC * HWS * HWS)
                                   : &g_feat[img][0][0][0];
    const __nv_bfloat16* Wh = (mode == 0) ? g_Wvh : g_Wch;
    const __nv_bfloat16* Wl = (mode == 0) ? g_Wvl : g_Wcl;

    // prefetch weight taps 0,1 (cp.async groups)
    #pragma unroll
    for (int s = 0; s < 2; s++) {
        for (int u = tid; u < 1024; u += 512) {
            int term = u >> 9, off = (u & 511) * 16;
            const char* gsrc = (const char*)((term ? Wl : Wh) + s * 4096) + off;
            cpa16(sb + CG_W + (uint32_t)s * 16384u + (uint32_t)(term * 8192 + off), gsrc);
        }
        cpa_commit();
    }

    // load X halo tile -> bf16 hi/lo swizzled [r][c]
    for (int base = 0; base < 42240; base += 512) {
        int idx = base + tid;
        if (idx < 42240) {
            int c  = idx / 660;
            int r  = idx - c * 660;
            int yy = r / 66;
            int xx = r - yy * 66;
            int gy = y0 - 1 + yy, gx = xx - 1;
            float v = 0.f;
            if (gy >= 0 && gy < 64 && gx >= 0 && gx < 64)
                v = src[c * 4096 + gy * 64 + gx];
            __nv_bfloat16 h = __float2bfloat16(v);
            __nv_bfloat16 l = __float2bfloat16(v - __bfloat162float(h));
            uint32_t o = (uint32_t)(r * 128 + 2 * (c ^ ((r & 7) << 3)));
            *(__nv_bfloat16*)(sm + CG_XH + o) = h;
            *(__nv_bfloat16*)(sm + CG_XL + o) = l;
        }
    }
    __syncthreads();

    // ---- main MMA loop over 9 taps ----
    float acc[2][8][4];
    #pragma unroll
    for (int mt = 0; mt < 2; mt++)
        #pragma unroll
        for (int nt = 0; nt < 8; nt++)
            #pragma unroll
            for (int q = 0; q < 4; q++) acc[mt][nt][q] = 0.f;

    for (int tap = 0; tap < 9; tap++) {
        const int ky = tap / 3;
        const int kx = tap - ky * 3;
        if (tap + 1 < 9) cpa_wait1(); else cpa_wait0();
        __syncthreads();
        const uint32_t wbuf = sb + CG_W + (uint32_t)(tap & 1) * 16384u;
        const int rbase = (wy + ky) * 66 + wx0 + lrow + kx;

        #pragma unroll
        for (int ks = 0; ks < 4; ks++) {
            const uint32_t cofs = (uint32_t)(ks * 32 + lhi * 16);
            uint32_t a[2][4], bh[4][4], bl[4][4];
            #pragma unroll
            for (int mt = 0; mt < 2; mt++) {
                int r = rbase + mt * 16;
                ldsm4(a[mt], sb + CG_XH + (uint32_t)(r * 128)
                             + (cofs ^ ((uint32_t)(r & 7) << 4)));
            }
            #pragma unroll
            for (int np = 0; np < 4; np++) {
                int o = np * 16 + lrow;
                ldsm4(bh[np], wbuf + (uint32_t)(o * 128)
                              + (cofs ^ ((uint32_t)(o & 7) << 4)));
            }
            #pragma unroll
            for (int mt = 0; mt < 2; mt++)
                #pragma unroll
                for (int nt = 0; nt < 8; nt++) {
                    uint32_t bf[2] = { bh[nt >> 1][nt & 1], bh[nt >> 1][(nt & 1) + 2] };
                    mma16816(acc[mt][nt], a[mt], bf);
                }
            #pragma unroll
            for (int np = 0; np < 4; np++) {
                int o = np * 16 + lrow;
                ldsm4(bl[np], wbuf + 8192u + (uint32_t)(o * 128)
                              + (cofs ^ ((uint32_t)(o & 7) << 4)));
            }
            #pragma unroll
            for (int mt = 0; mt < 2; mt++)
                #pragma unroll
                for (int nt = 0; nt < 8; nt++) {
                    uint32_t bf[2] = { bl[nt >> 1][nt & 1], bl[nt >> 1][(nt & 1) + 2] };
                    mma16816(acc[mt][nt], a[mt], bf);
                }
            #pragma unroll
            for (int mt = 0; mt < 2; mt++) {
                int r = rbase + mt * 16;
                ldsm4(a[mt], sb + CG_XL + (uint32_t)(r * 128)
                             + (cofs ^ ((uint32_t)(r & 7) << 4)));
            }
            #pragma unroll
            for (int mt = 0; mt < 2; mt++)
                #pragma unroll
                for (int nt = 0; nt < 8; nt++) {
                    uint32_t bf[2] = { bh[nt >> 1][nt & 1], bh[nt >> 1][(nt & 1) + 2] };
                    mma16816(acc[mt][nt], a[mt], bf);
                }
        }
        __syncthreads();
        if (tap + 2 < 9) {
            const int tp = tap + 2;
            const uint32_t dbuf = sb + CG_W + (uint32_t)(tp & 1) * 16384u;
            for (int u = tid; u < 1024; u += 512) {
                int term = u >> 9, off = (u & 511) * 16;
                const char* gsrc = (const char*)((term ? Wl : Wh) + tp * 4096) + off;
                cpa16(dbuf + (uint32_t)(term * 8192 + off), gsrc);
            }
            cpa_commit();
        }
    }

    // ---- stage D through smem (X area is dead now), then coalesced writeout ---
    float* Dbuf = (float*)sm;
    const int g  = lane >> 2;
    const int tq = lane & 3;
    #pragma unroll
    for (int mt = 0; mt < 2; mt++)
        #pragma unroll
        for (int rr = 0; rr < 2; rr++) {
            int px = wy * 64 + wx0 + mt * 16 + g + rr * 8;
            #pragma unroll
            for (int nt = 0; nt < 8; nt++) {
                int oc = nt * 8 + tq * 2;
                Dbuf[oc * DB_PITCH + px]       = acc[mt][nt][rr * 2];
                Dbuf[(oc + 1) * DB_PITCH + px] = acc[mt][nt][rr * 2 + 1];
            }
        }
    __syncthreads();

    if (mode == 0) {
        // fused transpose + hi/lo split: write Vt[d][tok] directly
        const int bb = img >> 4, tt = img & 15;
        const int tokbase = tt * 64 + ytile * 8;
        for (int e = tid; e < 32768; e += 512) {
            int d  = e >> 3, xb = e & 7;
            int oc = d >> 6, y = (d >> 3) & 7, xa = d & 7;
            float v = Dbuf[oc * DB_PITCH + y * 64 + xb * 8 + xa] + bias[oc];
            __nv_bfloat16 h = __float2bfloat16(v);
            g_Vth[bb][d][tokbase + xb] = h;
            g_Vtl[bb][d][tokbase + xb] = __float2bfloat16(v - __bfloat162float(h));
        }
    } else {
        for (int e = tid; e < 32768; e += 512) {
            int oc = e >> 9, y = (e >> 6) & 7, xx = e & 63;
            int gb = ((img * 64 + oc) * 64 + y0 + y) * 64 + xx;
            out[gb] = Dbuf[oc * DB_PITCH + y * 64 + xx] + bias[oc] + xin[gb];
        }
    }
}

// ---------------- mma.sync GEMM (both attention GEMMs) -------------------------
// CTA tile 128x128, warp tile 64x32 (2x4 warp grid), K-chunk 32. (R6 config)
#define OFF_AH   0u
#define OFF_AL   10240u                 // 128*80
#define OFF_BH   20480u
#define OFF_BL   30720u
#define STAGE_B  40960u

__device__ __forceinline__ void load_chunk32(
    uint32_t sb, int tid,
    const __nv_bfloat16* Ah, const __nv_bfloat16* Al, int i0,
    const __nv_bfloat16* Bh, const __nv_bfloat16* Bl, int j0,
    int ld, int k0)
{
    #pragma unroll
    for (int u = tid; u < 2048; u += 256) {
        int part = u >> 9;               // 0:Ah 1:Al 2:Bh 3:Bl
        int idx  = u & 511;              // 128 rows * 4 16B-chunks
        int r = idx >> 2, c = idx & 3;
        const __nv_bfloat16* src;
        if      (part == 0) src = Ah + (size_t)(i0 + r) * ld + k0 + c * 8;
        else if (part == 1) src = Al + (size_t)(i0 + r) * ld + k0 + c * 8;
        else if (part == 2) src = Bh + (size_t)(j0 + r) * ld + k0 + c * 8;
        else                src = Bl + (size_t)(j0 + r) * ld + k0 + c * 8;
        cpa16(sb + (uint32_t)part * 10240u + (uint32_t)(r * 80 + c * 16), src);
    }
    cpa_commit();
}

__global__ __launch_bounds__(256, 2) void gemm_mma_kernel(int mode)
{
    extern __shared__ char dsm[];
    const int tid  = threadIdx.x;
    const int wid  = tid >> 5;
    const int lane = tid & 31;
    const int g    = lane >> 2;          // 0..7
    const int t    = lane & 3;           // 0..3
    const int b    = blockIdx.z;
    const int i0   = blockIdx.y * 128;
    const int j0   = blockIdx.x * 128;
    const int wm   = (wid >> 2) * 64;
    const int wn   = (wid & 3) * 32;
    const int lrow = lane & 15;
    const int lk   = (lane >> 4) << 3;

    const __nv_bfloat16 *Ah, *Al, *Bh, *Bl;
    int ld, nch;
    if (mode == 0) {
        Ah = &g_Qh[b][0][0]; Al = &g_Ql[b][0][0];
        Bh = &g_Kh[b][0][0]; Bl = &g_Kl[b][0][0];
        ld = DIMD; nch = DIMD / 32;
    } else {
        Ah = &g_Ph[b][0][0]; Al = &g_Pl[b][0][0];
        Bh = &g_Vth[b][0][0]; Bl = &g_Vtl[b][0][0];
        ld = TOK; nch = TOK / 32;
    }

    const uint32_t sbase = smem_u32(dsm);
    float acc[4][4][4];
    #pragma unroll
    for (int mt = 0; mt < 4; mt++)
        #pragma unroll
        for (int nt = 0; nt < 4; nt++)
            #pragma unroll
            for (int q = 0; q < 4; q++) acc[mt][nt][q] = 0.f;

    load_chunk32(sbase,           tid, Ah, Al, i0, Bh, Bl, j0, ld, 0);
    load_chunk32(sbase + STAGE_B, tid, Ah, Al, i0, Bh, Bl, j0, ld, 32);

    for (int it = 0; it < nch; ++it) {
        const int p = it & 1;
        const uint32_t st = sbase + (uint32_t)p * STAGE_B;
        if (it + 1 < nch) cpa_wait1(); else cpa_wait0();
        __syncthreads();

        #pragma unroll
        for (int ks = 0; ks < 32; ks += 16) {
            uint32_t a[4][4], bh2[2][4], bl2[2][4];
            const uint32_t cofs = (uint32_t)((ks + lk) * 2);
            #pragma unroll
            for (int mt = 0; mt < 4; mt++)
                ldsm4(a[mt], st + OFF_AH + (uint32_t)((wm + mt * 16 + lrow) * 80) + cofs);
            #pragma unroll
            for (int ntp = 0; ntp < 2; ntp++)
                ldsm4(bh2[ntp], st + OFF_BH + (uint32_t)((wn + ntp * 16 + lrow) * 80) + cofs);
            #pragma unroll
            for (int mt = 0; mt < 4; mt++)
                #pragma unroll
                for (int nt = 0; nt < 4; nt++) {
                    uint32_t bf[2] = { bh2[nt >> 1][nt & 1], bh2[nt >> 1][(nt & 1) + 2] };
                    mma16816(acc[mt][nt], a[mt], bf);
                }
            #pragma unroll
            for (int ntp = 0; ntp < 2; ntp++)
                ldsm4(bl2[ntp], st + OFF_BL + (uint32_t)((wn + ntp * 16 + lrow) * 80) + cofs);
            #pragma unroll
            for (int mt = 0; mt < 4; mt++)
                #pragma unroll
                for (int nt = 0; nt < 4; nt++) {
                    uint32_t bf[2] = { bl2[nt >> 1][nt & 1], bl2[nt >> 1][(nt & 1) + 2] };
                    mma16816(acc[mt][nt], a[mt], bf);
                }
            #pragma unroll
            for (int mt = 0; mt < 4; mt++)
                ldsm4(a[mt], st + OFF_AL + (uint32_t)((wm + mt * 16 + lrow) * 80) + cofs);
            #pragma unroll
            for (int mt = 0; mt < 4; mt++)
                #pragma unroll
                for (int nt = 0; nt < 4; nt++) {
                    uint32_t bf[2] = { bh2[nt >> 1][nt & 1], bh2[nt >> 1][(nt & 1) + 2] };
                    mma16816(acc[mt][nt], a[mt], bf);
                }
        }
        __syncthreads();
        if (it + 2 < nch)
            load_chunk32(sbase + (uint32_t)p * STAGE_B, tid,
                         Ah, Al, i0, Bh, Bl, j0, ld, (it + 2) * 32);
    }

    if (mode == 0) {
        float* Sb = &g_S[b][0][0];
        const float scale = 0.015625f;       // 4096^-0.5
        #pragma unroll
        for (int mt = 0; mt < 4; mt++) {
            int r0 = i0 + wm + mt * 16 + g;
            #pragma unroll
            for (int nt = 0; nt < 4; nt++) {
                int col = j0 + wn + nt * 8 + t * 2;
                float2 lo = make_float2(acc[mt][nt][0] * scale, acc[mt][nt][1] * scale);
                float2 hi = make_float2(acc[mt][nt][2] * scale, acc[mt][nt][3] * scale);
                *(float2*)&Sb[(size_t)r0 * TOK + col]       = lo;
                *(float2*)&Sb[(size_t)(r0 + 8) * TOK + col] = hi;
            }
        }
    } else {
        #pragma unroll
        for (int mt = 0; mt < 4; mt++) {
            #pragma unroll
            for (int rr = 0; rr < 2; rr++) {
                int i   = i0 + wm + mt * 16 + g + rr * 8;
                int img = b * 16 + (i >> 6);
                int gh  = (i >> 3) & 7;
                int gw  = i & 7;
                #pragma unroll
                for (int nt = 0; nt < 4; nt++) {
                    int d  = j0 + wn + nt * 8 + t * 2;
                    int oc = d >> 6;
                    int pi = (d >> 3) & 7;
                    int pj = d & 7;
                    float2 o = make_float2(acc[mt][nt][rr * 2], acc[mt][nt][rr * 2 + 1]);
                    *(float2*)&g_feat[img][oc][gh * 8 + pi][gw * 8 + pj] = o;
                }
            }
        }
    }
}

// ---------------- kernel: row softmax, writes P hi/lo bf16 ---------------------
__global__ __launch_bounds__(128) void softmax_kernel() {
    const int row = blockIdx.x;            // 0..4095
    const float* p = &g_S[0][0][0] + (size_t)row * TOK;
    __nv_bfloat16* ph = &g_Ph[0][0][0] + (size_t)row * TOK;
    __nv_bfloat16* pl = &g_Pl[0][0][0] + (size_t)row * TOK;
    const int tid = threadIdx.x;
    float v[8];
    float m = -1e30f;
    #pragma unroll
    for (int i = 0; i < 8; i++) { v[i] = p[tid + (i << 7)]; m = fmaxf(m, v[i]); }
    #pragma unroll
    for (int o = 16; o > 0; o >>= 1) m = fmaxf(m, __shfl_xor_sync(0xffffffffu, m, o));
    __shared__ float redm[4], reds[4];
    if ((tid & 31) == 0) redm[tid >> 5] = m;
    __syncthreads();
    m = fmaxf(fmaxf(redm[0], redm[1]), fmaxf(redm[2], redm[3]));
    float sum = 0.f;
    #pragma unroll
    for (int i = 0; i < 8; i++) { v[i] = __expf(v[i] - m); sum += v[i]; }
    #pragma unroll
    for (int o = 16; o > 0; o >>= 1) sum += __shfl_xor_sync(0xffffffffu, sum, o);
    if ((tid & 31) == 0) reds[tid >> 5] = sum;
    __syncthreads();
    sum = reds[0] + reds[1] + reds[2] + reds[3];
    float inv = 1.0f / sum;
    #pragma unroll
    for (int i = 0; i < 8; i++) {
        float pv = v[i] * inv;
        __nv_bfloat16 h = __float2bfloat16(pv);
        ph[tid + (i << 7)] = h;
        pl[tid + (i << 7)] = __float2bfloat16(pv - __bfloat162float(h));
    }
}

// ---------------- launcher ----------------------------------------------------
extern "C" void kernel_launch(void* const* d_in, const int* in_sizes, int n_in,
                              void* d_out, int out_size) {
    (void)in_sizes; (void)n_in; (void)out_size;
    const float* x  = (const float*)d_in[0];
    const float* qw = (const float*)d_in[1];
    const float* qb = (const float*)d_in[2];
    const float* kw = (const float*)d_in[3];
    const float* kb = (const float*)d_in[4];
    const float* vw = (const float*)d_in[5];
    const float* vb = (const float*)d_in[6];
    const float* cw = (const float*)d_in[7];
    const float* cb = (const float*)d_in[8];
    float* out = (float*)d_out;

    const int dsmem = 64 * 10 * 66 * sizeof(float);   // 168,960 B
    const int gsmem = 2 * (int)STAGE_B;               // 81,920 B
    cudaFuncSetAttribute(dwqk_kernel,      cudaFuncAttributeMaxDynamicSharedMemorySize, dsmem);
    cudaFuncSetAttribute(conv_gemm_kernel, cudaFuncAttributeMaxDynamicSharedMemorySize, CG_SMEM);
    cudaFuncSetAttribute(gemm_mma_kernel,  cudaFuncAttributeMaxDynamicSharedMemorySize, gsmem);

    // s0 (default): prep_w -> dwqk -> gemm0 -> softmax -> [join] gemm1 -> conv1
    // s1 (side)   :        \-> conv0 (V conv, independent of attention front-end)
    prep_w_kernel<<<(9 * 64 * 64 + 255) / 256, 256>>>(vw, cw);
    cudaEventRecord(g_ss.e0, 0);
    cudaStreamWaitEvent(g_ss.s1, g_ss.e0, 0);
    conv_gemm_kernel<<<dim3(64, 8), 512, CG_SMEM, g_ss.s1>>>(0, x, vb, nullptr);
    cudaEventRecord(g_ss.e1, g_ss.s1);

    dwqk_kernel<<<dim3(64, 8), 512, dsmem>>>(x, qw, qb, kw, kb);
    gemm_mma_kernel<<<dim3(8, 8, NB), 256, gsmem>>>(0);    // S = QK^T * scale
    softmax_kernel<<<NB * TOK, 128>>>();
    cudaStreamWaitEvent(0, g_ss.e1, 0);
    gemm_mma_kernel<<<dim3(32, 8, NB), 256, gsmem>>>(1);   // feat = fold(P V)
    conv_gemm_kernel<<<dim3(64, 8), 512, CG_SMEM>>>(1, x, cb, out);
}